// round 8
// baseline (speedup 1.0000x reference)
#include <cuda_runtime.h>
#include <cuda_bf16.h>
#include <cstdint>

#define MAXN 100000
#define MAXE 1600000
#define DIM 128

// ---------------- device scratch ----------------
__device__ float g_all[(size_t)MAXN * 512];        // [N][512] concat embeddings
__device__ float g_ego[2][(size_t)MAXN * DIM];     // ping-pong ego (unnormalized)
__device__ __nv_bfloat16 g_wbf_hi[3 * 128 * 256];  // [layer][j][k] combined W rows, bf16 hi
__device__ __nv_bfloat16 g_wbf_lo[3 * 128 * 256];  // bf16 lo residual
__device__ float g_bias[3 * 128];
// CSR
__device__ int   g_deg[MAXN];
__device__ int   g_off[MAXN];      // after fill: end offset of node n
__device__ int   g_bsum[256];
__device__ int2  g_ecw[MAXE];      // packed {col, weight-bits}

// ================= helpers =================
__device__ __forceinline__ uint32_t smem_u32(const void* p) {
    uint32_t a;
    asm("{ .reg .u64 t; cvta.to.shared.u64 t, %1; cvt.u32.u64 %0, t; }" : "=r"(a) : "l"(p));
    return a;
}
#define LDSM_X4(r, addr) \
    asm volatile("ldmatrix.sync.aligned.m8n8.x4.shared.b16 {%0,%1,%2,%3}, [%4];" \
        : "=r"((r)[0]), "=r"((r)[1]), "=r"((r)[2]), "=r"((r)[3]) : "r"(addr))

__device__ __forceinline__ void mma16816(float* c, const uint32_t* a, const uint32_t* b) {
    asm volatile("mma.sync.aligned.m16n8k16.row.col.f32.bf16.bf16.f32 "
        "{%0,%1,%2,%3}, {%4,%5,%6,%7}, {%8,%9}, {%0,%1,%2,%3};"
        : "+f"(c[0]), "+f"(c[1]), "+f"(c[2]), "+f"(c[3])
        : "r"(a[0]), "r"(a[1]), "r"(a[2]), "r"(a[3]), "r"(b[0]), "r"(b[1]));
}
__device__ __forceinline__ void cp_async16(uint32_t smem, const void* g) {
    asm volatile("cp.async.cg.shared.global [%0], [%1], 16;" :: "r"(smem), "l"(g) : "memory");
}
#define CP_COMMIT() asm volatile("cp.async.commit_group;" ::: "memory")
#define CP_WAIT1() asm volatile("cp.async.wait_group 1;" ::: "memory")
#define CP_WAIT0() asm volatile("cp.async.wait_group 0;" ::: "memory")

__device__ __forceinline__ void split_pair(float x, float y, uint32_t& hi, uint32_t& lo) {
    __nv_bfloat162 h = __floats2bfloat162_rn(x, y);
    __nv_bfloat162 l = __floats2bfloat162_rn(x - __bfloat162float(h.x), y - __bfloat162float(h.y));
    hi = *reinterpret_cast<uint32_t*>(&h);
    lo = *reinterpret_cast<uint32_t*>(&l);
}

// ---------------- prep ----------------
__global__ void prep_kernel(const float* __restrict__ gcw, const float* __restrict__ gcb,
                            const float* __restrict__ biw, const float* __restrict__ bib) {
    int t = blockIdx.x * blockDim.x + threadIdx.x;
    if (t >= 3 * 128 * 256) return;
    int i = t >> 15;
    int r = t & 32767;
    int j = r >> 8, k = r & 255;
    float v;
    if (k < 128) v = gcw[i * 16384 + j * 128 + k];
    else         v = biw[i * 16384 + j * 128 + (k - 128)];
    __nv_bfloat16 hi = __float2bfloat16_rn(v);
    __nv_bfloat16 lo = __float2bfloat16_rn(v - __bfloat162float(hi));
    g_wbf_hi[t] = hi;
    g_wbf_lo[t] = lo;
    if (k == 0) g_bias[i * 128 + j] = gcb[i * 128 + j] + bib[i * 128 + j];
}

// ---------------- init ----------------
__global__ void init_kernel(const float* __restrict__ emb, int N) {
    int t = blockIdx.x * blockDim.x + threadIdx.x;
    int total = N * 32;
    if (t >= total) return;
    int n = t / 32, f = t % 32;
    float4 v = ((const float4*)emb)[t];
    ((float4*)g_ego[0])[t] = v;
    ((float4*)g_all)[(size_t)n * 128 + f] = v;
}

// ---------------- CSR build ----------------
__global__ void csr_zero_kernel(int N) {
    for (int i = blockIdx.x * blockDim.x + threadIdx.x; i < N; i += gridDim.x * blockDim.x)
        g_deg[i] = 0;
}
__global__ void csr_hist_kernel(const int* __restrict__ ei, int E) {
    int e4 = blockIdx.x * blockDim.x + threadIdx.x;
    int E4 = E >> 2;
    for (int i = e4; i < E4; i += gridDim.x * blockDim.x) {
        int4 r = __ldg((const int4*)ei + i);
        atomicAdd(&g_deg[r.x], 1);
        atomicAdd(&g_deg[r.y], 1);
        atomicAdd(&g_deg[r.z], 1);
        atomicAdd(&g_deg[r.w], 1);
    }
    if (e4 == 0)
        for (int e = E4 * 4; e < E; e++) atomicAdd(&g_deg[ei[e]], 1);
}
__global__ void csr_scan_local_kernel(int N) {
    __shared__ int sm[1024];
    int b = blockIdx.x, t = threadIdx.x;
    int i = b * 1024 + t;
    int v = (i < N) ? g_deg[i] : 0;
    sm[t] = v;
    __syncthreads();
#pragma unroll
    for (int off = 1; off < 1024; off <<= 1) {
        int x = sm[t];
        int y = (t >= off) ? sm[t - off] : 0;
        __syncthreads();
        sm[t] = x + y;
        __syncthreads();
    }
    if (i < N) g_off[i] = sm[t] - v;   // exclusive
    if (t == 1023) g_bsum[b] = sm[t];
}
__global__ void csr_scan_bsum_kernel(int nblk) {
    __shared__ int sm[256];
    int t = threadIdx.x;
    int v = (t < nblk) ? g_bsum[t] : 0;
    sm[t] = v;
    __syncthreads();
#pragma unroll
    for (int off = 1; off < 256; off <<= 1) {
        int x = sm[t];
        int y = (t >= off) ? sm[t - off] : 0;
        __syncthreads();
        sm[t] = x + y;
        __syncthreads();
    }
    g_bsum[t] = sm[t] - v;
}
__global__ void csr_scan_add_kernel(int N) {
    int i = blockIdx.x * blockDim.x + threadIdx.x;
    if (i < N) g_off[i] += g_bsum[i >> 10];
}
__global__ void csr_fill_kernel(const int* __restrict__ ei, const float* __restrict__ wt, int E) {
    for (int e = blockIdx.x * blockDim.x + threadIdx.x; e < E; e += gridDim.x * blockDim.x) {
        int row = __ldg(ei + e);
        int col = __ldg(ei + E + e);
        float w = __ldg(wt + e);
        int pos = atomicAdd(&g_off[row], 1);
        g_ecw[pos] = make_int2(col, __float_as_int(w));
    }
}

// ================= FUSED gather + GEMM layer =================
// Block = 128 nodes x 128 out. 512 threads (16 warps).
// Phase 1: warp w gathers rows w*8..w*8+7, writes split-bf16 A tiles to SMEM.
// Phase 2: HMMA 3-pass (hi*hi + hi*lo + lo*hi), B double-buffered per kb via cp.async.
// SMEM: A_HI [4 kb][128r][8 chunks16B] @0 (64KB), A_LO @65536 (64KB),
//       B stages @131072: 2 x (hi 16KB + lo 16KB). Total 196608.
#define FA_HI 0
#define FA_LO 65536
#define FB    131072
#define LK_SMEM 196608
#define EPI_ROWPART 69632
#define EPI_SCALE   71680

__device__ __forceinline__ void issue_b_stage(char* smem, int layer, int kb, int buf, int tid) {
    const char* wh = (const char*)(g_wbf_hi) + (size_t)layer * 65536;
    const char* wl = (const char*)(g_wbf_lo) + (size_t)layer * 65536;
    uint32_t base = smem_u32(smem + FB + buf * 32768);
#pragma unroll
    for (int it = 0; it < 2; it++) {
        int idx = tid + 512 * it;           // 1024 chunks
        int r = idx >> 3, c = idx & 7;
        size_t so = (size_t)r * 512 + kb * 128 + c * 16;
        uint32_t ci = (uint32_t)(r * 8 + (c ^ (r & 7))) * 16;
        cp_async16(base + ci, wh + so);
        cp_async16(base + 16384 + ci, wl + so);
    }
}

__global__ __launch_bounds__(512, 1) void fused_layer_kernel(int sel, int layer, int N) {
    extern __shared__ char smem[];
    const uint32_t sb = smem_u32(smem);
    const int tid = threadIdx.x;
    const int wid = tid >> 5;
    const int lid = tid & 31;
    const int n0 = blockIdx.x * 128;

    issue_b_stage(smem, layer, 0, 0, tid);
    CP_COMMIT();
    issue_b_stage(smem, layer, 1, 1, tid);
    CP_COMMIT();

    // ---------- Phase 1: gather 8 nodes per warp, STS split-bf16 into A ----------
    {
        const float* __restrict__ ego = g_ego[sel];
        int kbm = lid >> 4;                     // 0..1 (k-chunk half: cols 0..63 / 64..127)
        int cm = (lid & 15) >> 1;               // chunk 0..7
        int off8 = (lid & 1) * 8;
#pragma unroll
        for (int nd = 0; nd < 8; nd++) {
            int row = wid * 8 + nd;
            int n = n0 + row;
            uint2 mh = make_uint2(0, 0), ml = mh, ph = mh, pl = mh;
            if (n < N) {
                int s = (n == 0) ? 0 : __ldg(g_off + n - 1);
                int e = __ldg(g_off + n);
                float4 acc = make_float4(0.f, 0.f, 0.f, 0.f);
                int i = s;
                for (; i + 4 <= e; i += 4) {
                    int2 p0 = __ldg(g_ecw + i);
                    int2 p1 = __ldg(g_ecw + i + 1);
                    int2 p2 = __ldg(g_ecw + i + 2);
                    int2 p3 = __ldg(g_ecw + i + 3);
                    float4 v0 = __ldg((const float4*)(ego + (size_t)p0.x * DIM) + lid);
                    float4 v1 = __ldg((const float4*)(ego + (size_t)p1.x * DIM) + lid);
                    float4 v2 = __ldg((const float4*)(ego + (size_t)p2.x * DIM) + lid);
                    float4 v3 = __ldg((const float4*)(ego + (size_t)p3.x * DIM) + lid);
                    float w0 = __int_as_float(p0.y), w1 = __int_as_float(p1.y);
                    float w2 = __int_as_float(p2.y), w3 = __int_as_float(p3.y);
                    acc.x += w0 * v0.x; acc.y += w0 * v0.y; acc.z += w0 * v0.z; acc.w += w0 * v0.w;
                    acc.x += w1 * v1.x; acc.y += w1 * v1.y; acc.z += w1 * v1.z; acc.w += w1 * v1.w;
                    acc.x += w2 * v2.x; acc.y += w2 * v2.y; acc.z += w2 * v2.z; acc.w += w2 * v2.w;
                    acc.x += w3 * v3.x; acc.y += w3 * v3.y; acc.z += w3 * v3.z; acc.w += w3 * v3.w;
                }
                for (; i < e; i++) {
                    int2 p = __ldg(g_ecw + i);
                    float w = __int_as_float(p.y);
                    float4 v = __ldg((const float4*)(ego + (size_t)p.x * DIM) + lid);
                    acc.x += w * v.x; acc.y += w * v.y; acc.z += w * v.z; acc.w += w * v.w;
                }
                float4 eg = __ldg((const float4*)(ego + (size_t)n * DIM) + lid);
                float4 pr = make_float4(acc.x * eg.x, acc.y * eg.y, acc.z * eg.z, acc.w * eg.w);
                split_pair(acc.x, acc.y, mh.x, ml.x);
                split_pair(acc.z, acc.w, mh.y, ml.y);
                split_pair(pr.x, pr.y, ph.x, pl.x);
                split_pair(pr.z, pr.w, ph.y, pl.y);
            }
            // lane lid covers H cols [lid*4, lid*4+4) of msg part (kb = kbm) and
            // the same cols of the ego*msg part (kb = 2 + kbm).
            uint32_t swc = (uint32_t)(row * 8 + (cm ^ (row & 7))) * 16 + off8;
            uint32_t basem = (uint32_t)(kbm * 16384) + swc;
            uint32_t basep = (uint32_t)((2 + kbm) * 16384) + swc;
            *(uint2*)(smem + FA_HI + basem) = mh;
            *(uint2*)(smem + FA_LO + basem) = ml;
            *(uint2*)(smem + FA_HI + basep) = ph;
            *(uint2*)(smem + FA_LO + basep) = pl;
        }
    }
    __syncthreads();

    // ---------- Phase 2: MMA ----------
    const int wm = wid & 7;     // rows wm*16
    const int wn = wid >> 3;    // cols wn*64
    float acc[8][4];
#pragma unroll
    for (int nt = 0; nt < 8; nt++)
#pragma unroll
        for (int c = 0; c < 4; c++) acc[nt][c] = 0.f;

#pragma unroll
    for (int kb = 0; kb < 4; kb++) {
        if (kb < 3) CP_WAIT1(); else CP_WAIT0();
        __syncthreads();
        uint32_t bbase = sb + FB + (kb & 1) * 32768;
        uint32_t abase = sb + FA_HI + kb * 16384;
#pragma unroll
        for (int ks = 0; ks < 4; ks++) {
            uint32_t ahi[4], alo[4];
            int lr = lid & 15, lk = lid >> 4;
            {
                int r = wm * 16 + lr;
                int kc = ks * 2 + lk;
                uint32_t off = (uint32_t)(r * 8 + (kc ^ (r & 7))) * 16;
                LDSM_X4(ahi, abase + off);
                LDSM_X4(alo, abase + 65536 + off);
            }
            uint32_t bhi[4][4], blo[4][4];
            int nr = (lid & 7) + ((lid >> 4) << 3);
            int nk = (lid >> 3) & 1;
#pragma unroll
            for (int np = 0; np < 4; np++) {
                int r = wn * 64 + np * 16 + nr;
                int kc = ks * 2 + nk;
                uint32_t off = (uint32_t)(r * 8 + (kc ^ (r & 7))) * 16;
                LDSM_X4(bhi[np], bbase + off);
                LDSM_X4(blo[np], bbase + 16384 + off);
            }
#pragma unroll
            for (int nt = 0; nt < 8; nt++) {
                const uint32_t* bh = &bhi[nt >> 1][(nt & 1) * 2];
                const uint32_t* bl = &blo[nt >> 1][(nt & 1) * 2];
                mma16816(acc[nt], ahi, bh);
                mma16816(acc[nt], ahi, bl);
                mma16816(acc[nt], alo, bh);
            }
        }
        __syncthreads();
        if (kb + 2 < 4) { issue_b_stage(smem, layer, kb + 2, kb & 1, tid); CP_COMMIT(); }
    }

    // ---------- epilogue ----------
    float* stage = (float*)smem;                      // [128][136] (reuses A region)
    float* rowpart = (float*)(smem + EPI_ROWPART);    // [128][2]
    const float* bias = g_bias + layer * 128;
    int qid = lid >> 2, qt = lid & 3;
    {
        int rA = wm * 16 + qid;
        int rB = rA + 8;
        float sqa = 0.f, sqb = 0.f;
#pragma unroll
        for (int nt = 0; nt < 8; nt++) {
            int col = wn * 64 + nt * 8 + 2 * qt;
            float b0 = __ldg(bias + col), b1 = __ldg(bias + col + 1);
            float* c = acc[nt];
            float x0 = c[0] + b0, x1 = c[1] + b1;
            float y0 = c[2] + b0, y1 = c[3] + b1;
            x0 = x0 > 0.f ? x0 : 0.2f * x0;
            x1 = x1 > 0.f ? x1 : 0.2f * x1;
            y0 = y0 > 0.f ? y0 : 0.2f * y0;
            y1 = y1 > 0.f ? y1 : 0.2f * y1;
            stage[rA * 136 + col] = x0;
            stage[rA * 136 + col + 1] = x1;
            stage[rB * 136 + col] = y0;
            stage[rB * 136 + col + 1] = y1;
            sqa += x0 * x0 + x1 * x1;
            sqb += y0 * y0 + y1 * y1;
        }
        sqa += __shfl_xor_sync(0xffffffffu, sqa, 1);
        sqa += __shfl_xor_sync(0xffffffffu, sqa, 2);
        sqb += __shfl_xor_sync(0xffffffffu, sqb, 1);
        sqb += __shfl_xor_sync(0xffffffffu, sqb, 2);
        if (qt == 0) {
            rowpart[rA * 2 + wn] = sqa;
            rowpart[rB * 2 + wn] = sqb;
        }
    }
    __syncthreads();
    float* scl = (float*)(smem + EPI_SCALE);
    if (tid < 128) {
        float tot = rowpart[tid * 2] + rowpart[tid * 2 + 1];
        scl[tid] = 1.0f / fmaxf(sqrtf(tot), 1e-12f);
    }
    __syncthreads();
    float* ego_out = g_ego[sel ^ 1];
    int seg = (layer + 1) * 128;
#pragma unroll
    for (int it = 0; it < 8; it++) {
        int idx = tid + 512 * it;           // [128 rows][32 f4]
        int r = idx >> 5, j = idx & 31;
        int n = n0 + r;
        if (n < N) {
            float4 v = *(const float4*)(stage + r * 136 + j * 4);
            ((float4*)(ego_out + (size_t)n * DIM))[j] = v;
            float s = scl[r];
            float4 sv = make_float4(v.x * s, v.y * s, v.z * s, v.w * s);
            ((float4*)(g_all + (size_t)n * 512 + seg))[j] = sv;
        }
    }
}

// ---------------- scoring ----------------
__global__ void score_kernel(const int* __restrict__ eli, float* __restrict__ out, int Q) {
    int g = blockIdx.x * blockDim.x + threadIdx.x;
    int q = g >> 5;
    if (q >= Q) return;
    int lane = g & 31;
    int s = __ldg(eli + q);
    int d = __ldg(eli + Q + q);
    const float4* ps = (const float4*)(g_all + (size_t)s * 512);
    const float4* pd = (const float4*)(g_all + (size_t)d * 512);
    float sum = 0.f;
#pragma unroll
    for (int t = 0; t < 4; t++) {
        float4 a = __ldg(ps + lane + 32 * t);
        float4 b = __ldg(pd + lane + 32 * t);
        sum += a.x * b.x + a.y * b.y + a.z * b.z + a.w * b.w;
    }
#pragma unroll
    for (int off = 16; off > 0; off >>= 1)
        sum += __shfl_xor_sync(0xffffffffu, sum, off);
    if (lane == 0) out[q] = sum;
}

// ---------------- launch ----------------
extern "C" void kernel_launch(void* const* d_in, const int* in_sizes, int n_in,
                              void* d_out, int out_size) {
    const int*   ei  = (const int*)d_in[0];
    const int*   eli = (const int*)d_in[1];
    const float* wt  = (const float*)d_in[2];
    const float* emb = (const float*)d_in[3];
    const float* gcw = (const float*)d_in[4];
    const float* gcb = (const float*)d_in[5];
    const float* biw = (const float*)d_in[6];
    const float* bib = (const float*)d_in[7];

    int E = in_sizes[2];
    int Q = in_sizes[1] / 2;
    int N = in_sizes[3] / DIM;

    static bool attr_set = false;
    if (!attr_set) {
        cudaFuncSetAttribute(fused_layer_kernel, cudaFuncAttributeMaxDynamicSharedMemorySize, LK_SMEM);
        attr_set = true;
    }

    prep_kernel<<<(3 * 128 * 256 + 255) / 256, 256>>>(gcw, gcb, biw, bib);
    init_kernel<<<(N * 32 + 255) / 256, 256>>>(emb, N);

    int nblk = (N + 1023) / 1024;
    csr_zero_kernel<<<128, 256>>>(N);
    csr_hist_kernel<<<512, 256>>>(ei, E);
    csr_scan_local_kernel<<<nblk, 1024>>>(N);
    csr_scan_bsum_kernel<<<1, 256>>>(nblk);
    csr_scan_add_kernel<<<(N + 255) / 256, 256>>>(N);
    csr_fill_kernel<<<1024, 256>>>(ei, wt, E);

    int sel = 0;
    for (int i = 0; i < 3; i++) {
        fused_layer_kernel<<<(N + 127) / 128, 512, LK_SMEM>>>(sel, i, N);
        sel ^= 1;
    }
    score_kernel<<<(Q * 32 + 255) / 256, 256>>>(eli, (float*)d_out, Q);
}

// round 9
// speedup vs baseline: 1.1890x; 1.1890x over previous
#include <cuda_runtime.h>
#include <cuda_bf16.h>
#include <cstdint>

#define MAXN 100000
#define MAXE 1600000
#define DIM 128

// ---------------- device scratch ----------------
__device__ float g_all[(size_t)MAXN * 512];        // [N][512] concat embeddings
__device__ float g_ego[2][(size_t)MAXN * DIM];     // ping-pong ego (unnormalized)
__device__ __nv_bfloat16 g_h_hi[(size_t)MAXN * 256];   // H=[msg|ego*msg] hi
__device__ __nv_bfloat16 g_h_lo[(size_t)MAXN * 256];   // H lo residual
__device__ __nv_bfloat16 g_wbf_hi[3 * 128 * 256];  // [layer][j][k] combined W rows, bf16 hi
__device__ __nv_bfloat16 g_wbf_lo[3 * 128 * 256];  // bf16 lo residual
__device__ float g_bias[3 * 128];
// CSR
__device__ int   g_deg[MAXN];
__device__ int   g_off[MAXN];      // after fill: end offset of node n
__device__ int   g_bsum[256];
__device__ int2  g_ecw[MAXE];      // packed {col, weight-bits}

// ================= helpers =================
__device__ __forceinline__ uint32_t smem_u32(const void* p) {
    uint32_t a;
    asm("{ .reg .u64 t; cvta.to.shared.u64 t, %1; cvt.u32.u64 %0, t; }" : "=r"(a) : "l"(p));
    return a;
}
#define LDSM_X4(r, addr) \
    asm volatile("ldmatrix.sync.aligned.m8n8.x4.shared.b16 {%0,%1,%2,%3}, [%4];" \
        : "=r"((r)[0]), "=r"((r)[1]), "=r"((r)[2]), "=r"((r)[3]) : "r"(addr))

__device__ __forceinline__ void mma16816(float* c, const uint32_t* a, const uint32_t* b) {
    asm volatile("mma.sync.aligned.m16n8k16.row.col.f32.bf16.bf16.f32 "
        "{%0,%1,%2,%3}, {%4,%5,%6,%7}, {%8,%9}, {%0,%1,%2,%3};"
        : "+f"(c[0]), "+f"(c[1]), "+f"(c[2]), "+f"(c[3])
        : "r"(a[0]), "r"(a[1]), "r"(a[2]), "r"(a[3]), "r"(b[0]), "r"(b[1]));
}
__device__ __forceinline__ void cp_async16(uint32_t smem, const void* g, uint32_t srcsize) {
    asm volatile("cp.async.cg.shared.global [%0], [%1], 16, %2;"
                 :: "r"(smem), "l"(g), "r"(srcsize) : "memory");
}
#define CP_COMMIT() asm volatile("cp.async.commit_group;" ::: "memory")
#define CP_WAIT1() asm volatile("cp.async.wait_group 1;" ::: "memory")
#define CP_WAIT0() asm volatile("cp.async.wait_group 0;" ::: "memory")

__device__ __forceinline__ void split_pair(float x, float y, uint32_t& hi, uint32_t& lo) {
    __nv_bfloat162 h = __floats2bfloat162_rn(x, y);
    __nv_bfloat162 l = __floats2bfloat162_rn(x - __bfloat162float(h.x), y - __bfloat162float(h.y));
    hi = *reinterpret_cast<uint32_t*>(&h);
    lo = *reinterpret_cast<uint32_t*>(&l);
}

// ---------------- prep ----------------
__global__ void prep_kernel(const float* __restrict__ gcw, const float* __restrict__ gcb,
                            const float* __restrict__ biw, const float* __restrict__ bib) {
    int t = blockIdx.x * blockDim.x + threadIdx.x;
    if (t >= 3 * 128 * 256) return;
    int i = t >> 15;
    int r = t & 32767;
    int j = r >> 8, k = r & 255;
    float v;
    if (k < 128) v = gcw[i * 16384 + j * 128 + k];
    else         v = biw[i * 16384 + j * 128 + (k - 128)];
    __nv_bfloat16 hi = __float2bfloat16_rn(v);
    __nv_bfloat16 lo = __float2bfloat16_rn(v - __bfloat162float(hi));
    g_wbf_hi[t] = hi;
    g_wbf_lo[t] = lo;
    if (k == 0) g_bias[i * 128 + j] = gcb[i * 128 + j] + bib[i * 128 + j];
}

// ---------------- init ----------------
__global__ void init_kernel(const float* __restrict__ emb, int N) {
    int t = blockIdx.x * blockDim.x + threadIdx.x;
    int total = N * 32;
    if (t >= total) return;
    int n = t / 32, f = t % 32;
    float4 v = ((const float4*)emb)[t];
    ((float4*)g_ego[0])[t] = v;
    ((float4*)g_all)[(size_t)n * 128 + f] = v;
}

// ---------------- CSR build ----------------
__global__ void csr_zero_kernel(int N) {
    for (int i = blockIdx.x * blockDim.x + threadIdx.x; i < N; i += gridDim.x * blockDim.x)
        g_deg[i] = 0;
}
__global__ void csr_hist_kernel(const int* __restrict__ ei, int E) {
    int e4 = blockIdx.x * blockDim.x + threadIdx.x;
    int E4 = E >> 2;
    for (int i = e4; i < E4; i += gridDim.x * blockDim.x) {
        int4 r = __ldg((const int4*)ei + i);
        atomicAdd(&g_deg[r.x], 1);
        atomicAdd(&g_deg[r.y], 1);
        atomicAdd(&g_deg[r.z], 1);
        atomicAdd(&g_deg[r.w], 1);
    }
    if (e4 == 0)
        for (int e = E4 * 4; e < E; e++) atomicAdd(&g_deg[ei[e]], 1);
}
__global__ void csr_scan_local_kernel(int N) {
    __shared__ int sm[1024];
    int b = blockIdx.x, t = threadIdx.x;
    int i = b * 1024 + t;
    int v = (i < N) ? g_deg[i] : 0;
    sm[t] = v;
    __syncthreads();
#pragma unroll
    for (int off = 1; off < 1024; off <<= 1) {
        int x = sm[t];
        int y = (t >= off) ? sm[t - off] : 0;
        __syncthreads();
        sm[t] = x + y;
        __syncthreads();
    }
    if (i < N) g_off[i] = sm[t] - v;   // exclusive
    if (t == 1023) g_bsum[b] = sm[t];
}
__global__ void csr_scan_bsum_kernel(int nblk) {
    __shared__ int sm[256];
    int t = threadIdx.x;
    int v = (t < nblk) ? g_bsum[t] : 0;
    sm[t] = v;
    __syncthreads();
#pragma unroll
    for (int off = 1; off < 256; off <<= 1) {
        int x = sm[t];
        int y = (t >= off) ? sm[t - off] : 0;
        __syncthreads();
        sm[t] = x + y;
        __syncthreads();
    }
    g_bsum[t] = sm[t] - v;
}
__global__ void csr_scan_add_kernel(int N) {
    int i = blockIdx.x * blockDim.x + threadIdx.x;
    if (i < N) g_off[i] += g_bsum[i >> 10];
}
__global__ void csr_fill_kernel(const int* __restrict__ ei, const float* __restrict__ wt, int E) {
    for (int e = blockIdx.x * blockDim.x + threadIdx.x; e < E; e += gridDim.x * blockDim.x) {
        int row = __ldg(ei + e);
        int col = __ldg(ei + E + e);
        float w = __ldg(wt + e);
        int pos = atomicAdd(&g_off[row], 1);
        g_ecw[pos] = make_int2(col, __float_as_int(w));
    }
}

// ---------------- gather: msg = A@ego, emit H=[msg|ego*msg] split-bf16 ----------------
__global__ void gather_kernel(int sel, int N) {
    int g = blockIdx.x * blockDim.x + threadIdx.x;
    int n = g >> 5;
    if (n >= N) return;
    int lane = g & 31;
    int s = (n == 0) ? 0 : __ldg(g_off + n - 1);
    int e = __ldg(g_off + n);
    const float* __restrict__ ego = g_ego[sel];
    // independent self-row load issued early (adds MLP)
    float4 eg = __ldg((const float4*)(ego + (size_t)n * DIM) + lane);
    float4 acc = make_float4(0.f, 0.f, 0.f, 0.f);
    int i = s;
    // main loop: 8 edges in flight
    for (; i + 8 <= e; i += 8) {
        int2 p[8];
#pragma unroll
        for (int j = 0; j < 8; j++) p[j] = __ldg(g_ecw + i + j);
        float4 v[8];
#pragma unroll
        for (int j = 0; j < 8; j++)
            v[j] = __ldg((const float4*)(ego + (size_t)p[j].x * DIM) + lane);
#pragma unroll
        for (int j = 0; j < 8; j++) {
            float w = __int_as_float(p[j].y);
            acc.x += w * v[j].x; acc.y += w * v[j].y;
            acc.z += w * v[j].z; acc.w += w * v[j].w;
        }
    }
    if (i + 4 <= e) {
        int2 p[4];
#pragma unroll
        for (int j = 0; j < 4; j++) p[j] = __ldg(g_ecw + i + j);
        float4 v[4];
#pragma unroll
        for (int j = 0; j < 4; j++)
            v[j] = __ldg((const float4*)(ego + (size_t)p[j].x * DIM) + lane);
#pragma unroll
        for (int j = 0; j < 4; j++) {
            float w = __int_as_float(p[j].y);
            acc.x += w * v[j].x; acc.y += w * v[j].y;
            acc.z += w * v[j].z; acc.w += w * v[j].w;
        }
        i += 4;
    }
    for (; i < e; i++) {
        int2 p = __ldg(g_ecw + i);
        float w = __int_as_float(p.y);
        float4 v = __ldg((const float4*)(ego + (size_t)p.x * DIM) + lane);
        acc.x += w * v.x; acc.y += w * v.y; acc.z += w * v.z; acc.w += w * v.w;
    }
    float4 pr = make_float4(acc.x * eg.x, acc.y * eg.y, acc.z * eg.z, acc.w * eg.w);

    char* hi_row = (char*)(g_h_hi + (size_t)n * 256);
    char* lo_row = (char*)(g_h_lo + (size_t)n * 256);
    uint2 mh, ml, ph, pl;
    split_pair(acc.x, acc.y, mh.x, ml.x);
    split_pair(acc.z, acc.w, mh.y, ml.y);
    split_pair(pr.x, pr.y, ph.x, pl.x);
    split_pair(pr.z, pr.w, ph.y, pl.y);
    *(uint2*)(hi_row + lane * 8) = mh;
    *(uint2*)(lo_row + lane * 8) = ml;
    *(uint2*)(hi_row + 256 + lane * 8) = ph;
    *(uint2*)(lo_row + 256 + lane * 8) = pl;
}

// ================= layer GEMM: pipelined cp.async + mma.sync (bf16x3) =================
// Block 128x128, K=256 in 4 stages of 64. 256 threads, 8 warps, warp tile 64x32.
#define SMEM_B_HI 0          // 65536
#define SMEM_B_LO 65536      // 65536
#define SMEM_A    131072     // 2 stages x (Ahi 16KB + Alo 16KB)
#define LK_SMEM   196608
#define EPI_ROWPART 69632    // float [128][4]  (reuses B region post-MMA)
#define EPI_SCALE   71680    // float [128]

__device__ __forceinline__ void issue_a_stage(char* smem, int kb, int buf, int n0, int N, int tid) {
    uint32_t abase = smem_u32(smem + SMEM_A + buf * 32768);
    const char* hsrc = (const char*)g_h_hi;
    const char* lsrc = (const char*)g_h_lo;
#pragma unroll
    for (int it = 0; it < 4; it++) {
        int idx = tid + 256 * it;           // 1024 chunks
        int row = idx >> 3, c = idx & 7;
        int n = n0 + row;
        uint32_t sz = (n < N) ? 16u : 0u;
        size_t so = (size_t)(n < N ? n : 0) * 512 + kb * 128 + c * 16;
        uint32_t ci = (uint32_t)(row * 8 + (c ^ (row & 7))) * 16;
        cp_async16(abase + ci, hsrc + so, sz);
        cp_async16(abase + 16384 + ci, lsrc + so, sz);
    }
}

__global__ __launch_bounds__(256, 1) void layer_kernel(int sel, int layer, int N) {
    extern __shared__ char smem[];
    const uint32_t sb = smem_u32(smem);
    const int tid = threadIdx.x;
    const int wid = tid >> 5;
    const int lid = tid & 31;
    const int n0 = blockIdx.x * 128;
    const int wm = wid >> 2;
    const int wn = wid & 3;

    // ---- resident B (full layer W, hi+lo, 128KB) + A stages ----
    {
        const char* wh = (const char*)(g_wbf_hi) + (size_t)layer * 65536;
        const char* wl = (const char*)(g_wbf_lo) + (size_t)layer * 65536;
        uint32_t bh = sb + SMEM_B_HI, bl = sb + SMEM_B_LO;
#pragma unroll
        for (int it = 0; it < 16; it++) {
            int idx = tid + 256 * it;       // 4096 chunks: [kb 4][row 128][c 8]
            int kb = idx >> 10;
            int r = (idx >> 3) & 127;
            int c = idx & 7;
            size_t so = (size_t)r * 512 + kb * 128 + c * 16;
            uint32_t ci = (uint32_t)(kb * 16384) + (uint32_t)(r * 8 + (c ^ (r & 7))) * 16;
            cp_async16(bh + ci, wh + so, 16);
            cp_async16(bl + ci, wl + so, 16);
        }
    }
    issue_a_stage(smem, 0, 0, n0, N, tid);
    CP_COMMIT();
    issue_a_stage(smem, 1, 1, n0, N, tid);
    CP_COMMIT();

    float acc[4][4][4];
#pragma unroll
    for (int mt = 0; mt < 4; mt++)
#pragma unroll
        for (int nt = 0; nt < 4; nt++)
#pragma unroll
            for (int c = 0; c < 4; c++) acc[mt][nt][c] = 0.f;

#pragma unroll
    for (int kb = 0; kb < 4; kb++) {
        if (kb < 3) CP_WAIT1(); else CP_WAIT0();
        __syncthreads();

        uint32_t abase = sb + SMEM_A + (kb & 1) * 32768;
        uint32_t bhbase = sb + SMEM_B_HI + kb * 16384;
        uint32_t blbase = sb + SMEM_B_LO + kb * 16384;
#pragma unroll
        for (int ks = 0; ks < 4; ks++) {
            uint32_t ahi[4][4], alo[4][4];
            int lr = lid & 15, lk = lid >> 4;
#pragma unroll
            for (int mt = 0; mt < 4; mt++) {
                int r = wm * 64 + mt * 16 + lr;
                int kc = ks * 2 + lk;
                uint32_t off = (uint32_t)(r * 8 + (kc ^ (r & 7))) * 16;
                LDSM_X4(ahi[mt], abase + off);
                LDSM_X4(alo[mt], abase + 16384 + off);
            }
            uint32_t bhi[2][4], blo[2][4];
            int nr = (lid & 7) + ((lid >> 4) << 3);
            int nk = (lid >> 3) & 1;
#pragma unroll
            for (int np = 0; np < 2; np++) {
                int r = wn * 32 + np * 16 + nr;
                int kc = ks * 2 + nk;
                uint32_t off = (uint32_t)(r * 8 + (kc ^ (r & 7))) * 16;
                LDSM_X4(bhi[np], bhbase + off);
                LDSM_X4(blo[np], blbase + off);
            }
#pragma unroll
            for (int mt = 0; mt < 4; mt++)
#pragma unroll
                for (int nt = 0; nt < 4; nt++) {
                    const uint32_t* bh = &bhi[nt >> 1][(nt & 1) * 2];
                    const uint32_t* bl = &blo[nt >> 1][(nt & 1) * 2];
                    mma16816(acc[mt][nt], ahi[mt], bh);
                    mma16816(acc[mt][nt], ahi[mt], bl);
                    mma16816(acc[mt][nt], alo[mt], bh);
                }
        }
        __syncthreads();
        if (kb + 2 < 4) { issue_a_stage(smem, kb + 2, kb & 1, n0, N, tid); CP_COMMIT(); }
    }

    // ================= epilogue (reuses B SMEM region) =================
    float* stage = (float*)smem;                      // [128][136]
    float* rowpart = (float*)(smem + EPI_ROWPART);    // [128][4]
    const float* bias = g_bias + layer * 128;
    int qid = lid >> 2, qt = lid & 3;
#pragma unroll
    for (int mt = 0; mt < 4; mt++) {
        int rA = wm * 64 + mt * 16 + qid;
        int rB = rA + 8;
        float sqa = 0.f, sqb = 0.f;
#pragma unroll
        for (int nt = 0; nt < 4; nt++) {
            int col = wn * 32 + nt * 8 + 2 * qt;
            float b0 = __ldg(bias + col), b1 = __ldg(bias + col + 1);
            float* c = acc[mt][nt];
            float x0 = c[0] + b0, x1 = c[1] + b1;
            float y0 = c[2] + b0, y1 = c[3] + b1;
            x0 = x0 > 0.f ? x0 : 0.2f * x0;
            x1 = x1 > 0.f ? x1 : 0.2f * x1;
            y0 = y0 > 0.f ? y0 : 0.2f * y0;
            y1 = y1 > 0.f ? y1 : 0.2f * y1;
            stage[rA * 136 + col] = x0;
            stage[rA * 136 + col + 1] = x1;
            stage[rB * 136 + col] = y0;
            stage[rB * 136 + col + 1] = y1;
            sqa += x0 * x0 + x1 * x1;
            sqb += y0 * y0 + y1 * y1;
        }
        sqa += __shfl_xor_sync(0xffffffffu, sqa, 1);
        sqa += __shfl_xor_sync(0xffffffffu, sqa, 2);
        sqb += __shfl_xor_sync(0xffffffffu, sqb, 1);
        sqb += __shfl_xor_sync(0xffffffffu, sqb, 2);
        if (qt == 0) {
            rowpart[rA * 4 + wn] = sqa;
            rowpart[rB * 4 + wn] = sqb;
        }
    }
    __syncthreads();
    float* scl = (float*)(smem + EPI_SCALE);
    if (tid < 128) {
        float tot = rowpart[tid * 4] + rowpart[tid * 4 + 1] + rowpart[tid * 4 + 2] + rowpart[tid * 4 + 3];
        scl[tid] = 1.0f / fmaxf(sqrtf(tot), 1e-12f);
    }
    __syncthreads();
    float* ego_out = g_ego[sel ^ 1];
    int seg = (layer + 1) * 128;
#pragma unroll
    for (int it = 0; it < 16; it++) {
        int idx = tid + 256 * it;
        int r = idx >> 5, j = idx & 31;
        int n = n0 + r;
        if (n < N) {
            float4 v = *(const float4*)(stage + r * 136 + j * 4);
            ((float4*)(ego_out + (size_t)n * DIM))[j] = v;
            float s = scl[r];
            float4 sv = make_float4(v.x * s, v.y * s, v.z * s, v.w * s);
            ((float4*)(g_all + (size_t)n * 512 + seg))[j] = sv;
        }
    }
}

// ---------------- scoring ----------------
__global__ void score_kernel(const int* __restrict__ eli, float* __restrict__ out, int Q) {
    int g = blockIdx.x * blockDim.x + threadIdx.x;
    int q = g >> 5;
    if (q >= Q) return;
    int lane = g & 31;
    int s = __ldg(eli + q);
    int d = __ldg(eli + Q + q);
    const float4* ps = (const float4*)(g_all + (size_t)s * 512);
    const float4* pd = (const float4*)(g_all + (size_t)d * 512);
    float sum = 0.f;
#pragma unroll
    for (int t = 0; t < 4; t++) {
        float4 a = __ldg(ps + lane + 32 * t);
        float4 b = __ldg(pd + lane + 32 * t);
        sum += a.x * b.x + a.y * b.y + a.z * b.z + a.w * b.w;
    }
#pragma unroll
    for (int off = 16; off > 0; off >>= 1)
        sum += __shfl_xor_sync(0xffffffffu, sum, off);
    if (lane == 0) out[q] = sum;
}

// ---------------- launch ----------------
extern "C" void kernel_launch(void* const* d_in, const int* in_sizes, int n_in,
                              void* d_out, int out_size) {
    const int*   ei  = (const int*)d_in[0];
    const int*   eli = (const int*)d_in[1];
    const float* wt  = (const float*)d_in[2];
    const float* emb = (const float*)d_in[3];
    const float* gcw = (const float*)d_in[4];
    const float* gcb = (const float*)d_in[5];
    const float* biw = (const float*)d_in[6];
    const float* bib = (const float*)d_in[7];

    int E = in_sizes[2];
    int Q = in_sizes[1] / 2;
    int N = in_sizes[3] / DIM;

    static bool attr_set = false;
    if (!attr_set) {
        cudaFuncSetAttribute(layer_kernel, cudaFuncAttributeMaxDynamicSharedMemorySize, LK_SMEM);
        attr_set = true;
    }

    prep_kernel<<<(3 * 128 * 256 + 255) / 256, 256>>>(gcw, gcb, biw, bib);
    init_kernel<<<(N * 32 + 255) / 256, 256>>>(emb, N);

    int nblk = (N + 1023) / 1024;
    csr_zero_kernel<<<128, 256>>>(N);
    csr_hist_kernel<<<1024, 256>>>(ei, E);
    csr_scan_local_kernel<<<nblk, 1024>>>(N);
    csr_scan_bsum_kernel<<<1, 256>>>(nblk);
    csr_scan_add_kernel<<<(N + 255) / 256, 256>>>(N);
    csr_fill_kernel<<<1024, 256>>>(ei, wt, E);

    int sel = 0;
    for (int i = 0; i < 3; i++) {
        long long gthreads = (long long)N * 32;
        int gblocks = (int)((gthreads + 255) / 256);
        gather_kernel<<<gblocks, 256>>>(sel, N);
        layer_kernel<<<(N + 127) / 128, 256, LK_SMEM>>>(sel, i, N);
        sel ^= 1;
    }
    score_kernel<<<(Q * 32 + 255) / 256, 256>>>(eli, (float*)d_out, Q);
}

// round 10
// speedup vs baseline: 1.2863x; 1.0818x over previous
#include <cuda_runtime.h>
#include <cuda_bf16.h>
#include <cstdint>

#define MAXN 100000
#define MAXE 1600000
#define DIM 128

// ---------------- device scratch (no allocations allowed) ----------------
__device__ float g_all[(size_t)MAXN * 512];        // [N][512] concat embeddings
__device__ float g_ego[2][(size_t)MAXN * DIM];     // ping-pong ego buffers (unnormalized)
__device__ __nv_bfloat16 g_h_hi[(size_t)MAXN * 256];   // H=[msg|ego*msg] hi
__device__ __nv_bfloat16 g_h_lo[(size_t)MAXN * 256];   // H lo residual
__device__ __nv_bfloat16 g_wbf_hi[3 * 128 * 256];  // [layer][j][k] combined W rows, bf16 hi
__device__ __nv_bfloat16 g_wbf_lo[3 * 128 * 256];  // bf16 lo (residual)
__device__ float g_bias[3 * 128];                  // gc_b + bi_b
// CSR
__device__ int   g_deg[MAXN];
__device__ int   g_cur[MAXN];
__device__ int   g_off[MAXN + 1];
__device__ int   g_bsum[256];
__device__ int   g_ccol[MAXE];
__device__ float g_cw[MAXE];

// ================= helpers =================
__device__ __forceinline__ uint32_t smem_u32(const void* p) {
    uint32_t a;
    asm("{ .reg .u64 t; cvta.to.shared.u64 t, %1; cvt.u32.u64 %0, t; }" : "=r"(a) : "l"(p));
    return a;
}
#define LDSM_X4(r, addr) \
    asm volatile("ldmatrix.sync.aligned.m8n8.x4.shared.b16 {%0,%1,%2,%3}, [%4];" \
        : "=r"((r)[0]), "=r"((r)[1]), "=r"((r)[2]), "=r"((r)[3]) : "r"(addr))

__device__ __forceinline__ void mma16816(float* c, const uint32_t* a, const uint32_t* b) {
    asm volatile("mma.sync.aligned.m16n8k16.row.col.f32.bf16.bf16.f32 "
        "{%0,%1,%2,%3}, {%4,%5,%6,%7}, {%8,%9}, {%0,%1,%2,%3};"
        : "+f"(c[0]), "+f"(c[1]), "+f"(c[2]), "+f"(c[3])
        : "r"(a[0]), "r"(a[1]), "r"(a[2]), "r"(a[3]), "r"(b[0]), "r"(b[1]));
}
__device__ __forceinline__ void cp_async16(uint32_t smem, const void* g, uint32_t srcsize) {
    asm volatile("cp.async.cg.shared.global [%0], [%1], 16, %2;"
                 :: "r"(smem), "l"(g), "r"(srcsize) : "memory");
}
#define CP_COMMIT() asm volatile("cp.async.commit_group;" ::: "memory")
#define CP_WAIT1() asm volatile("cp.async.wait_group 1;" ::: "memory")
#define CP_WAIT0() asm volatile("cp.async.wait_group 0;" ::: "memory")

// ---------------- prep: combined W rows -> bf16 hi/lo, bias ----------------
__global__ void prep_kernel(const float* __restrict__ gcw, const float* __restrict__ gcb,
                            const float* __restrict__ biw, const float* __restrict__ bib) {
    int t = blockIdx.x * blockDim.x + threadIdx.x;
    if (t >= 3 * 128 * 256) return;
    int i = t >> 15;
    int r = t & 32767;
    int j = r >> 8, k = r & 255;
    float v;
    if (k < 128) v = gcw[i * 16384 + j * 128 + k];
    else         v = biw[i * 16384 + j * 128 + (k - 128)];
    __nv_bfloat16 hi = __float2bfloat16_rn(v);
    __nv_bfloat16 lo = __float2bfloat16_rn(v - __bfloat162float(hi));
    g_wbf_hi[t] = hi;
    g_wbf_lo[t] = lo;
    if (k == 0) g_bias[i * 128 + j] = gcb[i * 128 + j] + bib[i * 128 + j];
}

// ---------------- init ----------------
__global__ void init_kernel(const float* __restrict__ emb, int N) {
    int t = blockIdx.x * blockDim.x + threadIdx.x;
    int total = N * 32;
    if (t >= total) return;
    int n = t / 32, f = t % 32;
    float4 v = ((const float4*)emb)[t];
    ((float4*)g_ego[0])[t] = v;
    ((float4*)g_all)[(size_t)n * 128 + f] = v;
}

// ---------------- CSR build ----------------
__global__ void csr_zero_kernel(int N) {
    for (int i = blockIdx.x * blockDim.x + threadIdx.x; i < N; i += gridDim.x * blockDim.x) {
        g_deg[i] = 0;
        g_cur[i] = 0;
    }
}
__global__ void csr_hist_kernel(const int* __restrict__ ei, int E) {
    for (int e = blockIdx.x * blockDim.x + threadIdx.x; e < E; e += gridDim.x * blockDim.x)
        atomicAdd(&g_deg[ei[e]], 1);
}
__global__ void csr_scan_local_kernel(int N) {
    __shared__ int sm[1024];
    int b = blockIdx.x, t = threadIdx.x;
    int i = b * 1024 + t;
    int v = (i < N) ? g_deg[i] : 0;
    sm[t] = v;
    __syncthreads();
#pragma unroll
    for (int off = 1; off < 1024; off <<= 1) {
        int x = sm[t];
        int y = (t >= off) ? sm[t - off] : 0;
        __syncthreads();
        sm[t] = x + y;
        __syncthreads();
    }
    if (i < N) g_off[i] = sm[t] - v;
    if (t == 1023) g_bsum[b] = sm[t];
}
__global__ void csr_scan_bsum_kernel(int nblk) {
    __shared__ int sm[256];
    int t = threadIdx.x;
    int v = (t < nblk) ? g_bsum[t] : 0;
    sm[t] = v;
    __syncthreads();
#pragma unroll
    for (int off = 1; off < 256; off <<= 1) {
        int x = sm[t];
        int y = (t >= off) ? sm[t - off] : 0;
        __syncthreads();
        sm[t] = x + y;
        __syncthreads();
    }
    g_bsum[t] = sm[t] - v;
}
__global__ void csr_scan_add_kernel(int N, int E) {
    int i = blockIdx.x * blockDim.x + threadIdx.x;
    if (i < N) g_off[i] += g_bsum[i >> 10];
    if (i == 0) g_off[N] = E;
}
__global__ void csr_fill_kernel(const int* __restrict__ ei, const float* __restrict__ wt, int E) {
    for (int e = blockIdx.x * blockDim.x + threadIdx.x; e < E; e += gridDim.x * blockDim.x) {
        int row = ei[e];
        int pos = g_off[row] + atomicAdd(&g_cur[row], 1);
        g_ccol[pos] = ei[E + e];
        g_cw[pos] = wt[e];
    }
}

// ---------------- gather: msg = A@ego, then emit H=[msg|ego*msg] split-bf16 ----------------
__device__ __forceinline__ void split_pair(float x, float y, uint32_t& hi, uint32_t& lo) {
    __nv_bfloat162 h = __floats2bfloat162_rn(x, y);
    __nv_bfloat162 l = __floats2bfloat162_rn(x - __bfloat162float(h.x), y - __bfloat162float(h.y));
    hi = *reinterpret_cast<uint32_t*>(&h);
    lo = *reinterpret_cast<uint32_t*>(&l);
}

__global__ void gather_kernel(int sel, int N) {
    int g = blockIdx.x * blockDim.x + threadIdx.x;
    int n = g >> 5;
    if (n >= N) return;
    int lane = g & 31;
    int s = g_off[n], e = g_off[n + 1];
    const float* __restrict__ ego = g_ego[sel];
    float4 acc = make_float4(0.f, 0.f, 0.f, 0.f);
    int i = s;
    for (; i + 4 <= e; i += 4) {
        int c0 = __ldg(g_ccol + i), c1 = __ldg(g_ccol + i + 1);
        int c2 = __ldg(g_ccol + i + 2), c3 = __ldg(g_ccol + i + 3);
        float w0 = __ldg(g_cw + i), w1 = __ldg(g_cw + i + 1);
        float w2 = __ldg(g_cw + i + 2), w3 = __ldg(g_cw + i + 3);
        float4 v0 = __ldg((const float4*)(ego + (size_t)c0 * DIM) + lane);
        float4 v1 = __ldg((const float4*)(ego + (size_t)c1 * DIM) + lane);
        float4 v2 = __ldg((const float4*)(ego + (size_t)c2 * DIM) + lane);
        float4 v3 = __ldg((const float4*)(ego + (size_t)c3 * DIM) + lane);
        acc.x += w0 * v0.x; acc.y += w0 * v0.y; acc.z += w0 * v0.z; acc.w += w0 * v0.w;
        acc.x += w1 * v1.x; acc.y += w1 * v1.y; acc.z += w1 * v1.z; acc.w += w1 * v1.w;
        acc.x += w2 * v2.x; acc.y += w2 * v2.y; acc.z += w2 * v2.z; acc.w += w2 * v2.w;
        acc.x += w3 * v3.x; acc.y += w3 * v3.y; acc.z += w3 * v3.z; acc.w += w3 * v3.w;
    }
    for (; i < e; i++) {
        int c = __ldg(g_ccol + i);
        float w = __ldg(g_cw + i);
        float4 v = __ldg((const float4*)(ego + (size_t)c * DIM) + lane);
        acc.x += w * v.x; acc.y += w * v.y; acc.z += w * v.z; acc.w += w * v.w;
    }
    // own ego row (coalesced)
    float4 eg = __ldg((const float4*)(ego + (size_t)n * DIM) + lane);
    float4 pr = make_float4(acc.x * eg.x, acc.y * eg.y, acc.z * eg.z, acc.w * eg.w);

    char* hi_row = (char*)(g_h_hi + (size_t)n * 256);
    char* lo_row = (char*)(g_h_lo + (size_t)n * 256);
    uint2 mh, ml, ph, pl;
    split_pair(acc.x, acc.y, mh.x, ml.x);
    split_pair(acc.z, acc.w, mh.y, ml.y);
    split_pair(pr.x, pr.y, ph.x, pl.x);
    split_pair(pr.z, pr.w, ph.y, pl.y);
    *(uint2*)(hi_row + lane * 8) = mh;
    *(uint2*)(lo_row + lane * 8) = ml;
    *(uint2*)(hi_row + 256 + lane * 8) = ph;
    *(uint2*)(lo_row + 256 + lane * 8) = pl;
}

// ================= layer GEMM: pipelined cp.async + mma.sync (bf16x3) =================
// Block 128x128, K=256 in 4 stages of 64. 256 threads, 8 warps, warp tile 64x32.
#define SMEM_B_HI 0          // 65536
#define SMEM_B_LO 65536      // 65536
#define SMEM_A    131072     // 2 stages x (Ahi 16KB + Alo 16KB)
#define LK_SMEM   196608
#define EPI_ROWPART 69632    // float [128][4]  (reuses B region post-MMA)
#define EPI_SCALE   71680    // float [128]

__device__ __forceinline__ void issue_a_stage(char* smem, int kb, int buf, int n0, int N, int tid) {
    uint32_t abase = smem_u32(smem + SMEM_A + buf * 32768);
    const char* hsrc = (const char*)g_h_hi;
    const char* lsrc = (const char*)g_h_lo;
#pragma unroll
    for (int it = 0; it < 4; it++) {
        int idx = tid + 256 * it;           // 1024 chunks
        int row = idx >> 3, c = idx & 7;
        int n = n0 + row;
        uint32_t sz = (n < N) ? 16u : 0u;
        size_t so = (size_t)(n < N ? n : 0) * 512 + kb * 128 + c * 16;
        uint32_t ci = (uint32_t)(row * 8 + (c ^ (row & 7))) * 16;
        cp_async16(abase + ci, hsrc + so, sz);
        cp_async16(abase + 16384 + ci, lsrc + so, sz);
    }
}

__global__ __launch_bounds__(256, 1) void layer_kernel(int sel, int layer, int N) {
    extern __shared__ char smem[];
    const uint32_t sb = smem_u32(smem);
    const int tid = threadIdx.x;
    const int wid = tid >> 5;
    const int lid = tid & 31;
    const int n0 = blockIdx.x * 128;
    const int wm = wid >> 2;
    const int wn = wid & 3;

    // ---- resident B (full layer W, hi+lo, 128KB) + A stages ----
    {
        const char* wh = (const char*)(g_wbf_hi) + (size_t)layer * 65536;
        const char* wl = (const char*)(g_wbf_lo) + (size_t)layer * 65536;
        uint32_t bh = sb + SMEM_B_HI, bl = sb + SMEM_B_LO;
#pragma unroll
        for (int it = 0; it < 16; it++) {
            int idx = tid + 256 * it;       // 4096 chunks: [kb 4][row 128][c 8]
            int kb = idx >> 10;
            int r = (idx >> 3) & 127;
            int c = idx & 7;
            size_t so = (size_t)r * 512 + kb * 128 + c * 16;
            uint32_t ci = (uint32_t)(kb * 16384) + (uint32_t)(r * 8 + (c ^ (r & 7))) * 16;
            cp_async16(bh + ci, wh + so, 16);
            cp_async16(bl + ci, wl + so, 16);
        }
    }
    issue_a_stage(smem, 0, 0, n0, N, tid);
    CP_COMMIT();
    issue_a_stage(smem, 1, 1, n0, N, tid);
    CP_COMMIT();

    float acc[4][4][4];
#pragma unroll
    for (int mt = 0; mt < 4; mt++)
#pragma unroll
        for (int nt = 0; nt < 4; nt++)
#pragma unroll
            for (int c = 0; c < 4; c++) acc[mt][nt][c] = 0.f;

#pragma unroll
    for (int kb = 0; kb < 4; kb++) {
        if (kb < 3) CP_WAIT1(); else CP_WAIT0();
        __syncthreads();

        uint32_t abase = sb + SMEM_A + (kb & 1) * 32768;
        uint32_t bhbase = sb + SMEM_B_HI + kb * 16384;
        uint32_t blbase = sb + SMEM_B_LO + kb * 16384;
#pragma unroll
        for (int ks = 0; ks < 4; ks++) {
            uint32_t ahi[4][4], alo[4][4];
            int lr = lid & 15, lk = lid >> 4;
#pragma unroll
            for (int mt = 0; mt < 4; mt++) {
                int r = wm * 64 + mt * 16 + lr;
                int kc = ks * 2 + lk;
                uint32_t off = (uint32_t)(r * 8 + (kc ^ (r & 7))) * 16;
                LDSM_X4(ahi[mt], abase + off);
                LDSM_X4(alo[mt], abase + 16384 + off);
            }
            uint32_t bhi[2][4], blo[2][4];
            int nr = (lid & 7) + ((lid >> 4) << 3);
            int nk = (lid >> 3) & 1;
#pragma unroll
            for (int np = 0; np < 2; np++) {
                int r = wn * 32 + np * 16 + nr;
                int kc = ks * 2 + nk;
                uint32_t off = (uint32_t)(r * 8 + (kc ^ (r & 7))) * 16;
                LDSM_X4(bhi[np], bhbase + off);
                LDSM_X4(blo[np], blbase + off);
            }
#pragma unroll
            for (int mt = 0; mt < 4; mt++)
#pragma unroll
                for (int nt = 0; nt < 4; nt++) {
                    const uint32_t* bh = &bhi[nt >> 1][(nt & 1) * 2];
                    const uint32_t* bl = &blo[nt >> 1][(nt & 1) * 2];
                    mma16816(acc[mt][nt], ahi[mt], bh);
                    mma16816(acc[mt][nt], ahi[mt], bl);
                    mma16816(acc[mt][nt], alo[mt], bh);
                }
        }
        __syncthreads();
        if (kb + 2 < 4) { issue_a_stage(smem, kb + 2, kb & 1, n0, N, tid); CP_COMMIT(); }
    }

    // ================= epilogue (reuses B SMEM region) =================
    float* stage = (float*)smem;                      // [128][136]
    float* rowpart = (float*)(smem + EPI_ROWPART);    // [128][4]
    const float* bias = g_bias + layer * 128;
    int qid = lid >> 2, qt = lid & 3;
#pragma unroll
    for (int mt = 0; mt < 4; mt++) {
        int rA = wm * 64 + mt * 16 + qid;
        int rB = rA + 8;
        float sqa = 0.f, sqb = 0.f;
#pragma unroll
        for (int nt = 0; nt < 4; nt++) {
            int col = wn * 32 + nt * 8 + 2 * qt;
            float b0 = __ldg(bias + col), b1 = __ldg(bias + col + 1);
            float* c = acc[mt][nt];
            float x0 = c[0] + b0, x1 = c[1] + b1;
            float y0 = c[2] + b0, y1 = c[3] + b1;
            x0 = x0 > 0.f ? x0 : 0.2f * x0;
            x1 = x1 > 0.f ? x1 : 0.2f * x1;
            y0 = y0 > 0.f ? y0 : 0.2f * y0;
            y1 = y1 > 0.f ? y1 : 0.2f * y1;
            stage[rA * 136 + col] = x0;
            stage[rA * 136 + col + 1] = x1;
            stage[rB * 136 + col] = y0;
            stage[rB * 136 + col + 1] = y1;
            sqa += x0 * x0 + x1 * x1;
            sqb += y0 * y0 + y1 * y1;
        }
        sqa += __shfl_xor_sync(0xffffffffu, sqa, 1);
        sqa += __shfl_xor_sync(0xffffffffu, sqa, 2);
        sqb += __shfl_xor_sync(0xffffffffu, sqb, 1);
        sqb += __shfl_xor_sync(0xffffffffu, sqb, 2);
        if (qt == 0) {
            rowpart[rA * 4 + wn] = sqa;
            rowpart[rB * 4 + wn] = sqb;
        }
    }
    __syncthreads();
    float* scl = (float*)(smem + EPI_SCALE);
    if (tid < 128) {
        float tot = rowpart[tid * 4] + rowpart[tid * 4 + 1] + rowpart[tid * 4 + 2] + rowpart[tid * 4 + 3];
        scl[tid] = 1.0f / fmaxf(sqrtf(tot), 1e-12f);
    }
    __syncthreads();
    float* ego_out = g_ego[sel ^ 1];
    int seg = (layer + 1) * 128;
#pragma unroll
    for (int it = 0; it < 16; it++) {
        int idx = tid + 256 * it;
        int r = idx >> 5, j = idx & 31;
        int n = n0 + r;
        if (n < N) {
            float4 v = *(const float4*)(stage + r * 136 + j * 4);
            ((float4*)(ego_out + (size_t)n * DIM))[j] = v;
            float s = scl[r];
            float4 sv = make_float4(v.x * s, v.y * s, v.z * s, v.w * s);
            ((float4*)(g_all + (size_t)n * 512 + seg))[j] = sv;
        }
    }
}

// ---------------- scoring: 16 lanes per query (2 queries/warp, 16 LDG.128 in flight/lane) ----------------
__global__ void score_kernel(const int* __restrict__ eli, float* __restrict__ out, int Q) {
    int g = blockIdx.x * blockDim.x + threadIdx.x;
    int q = g >> 4;
    if (q >= Q) return;
    int lane = g & 15;
    int s = __ldg(eli + q);
    int d = __ldg(eli + Q + q);
    const float4* ps = (const float4*)(g_all + (size_t)s * 512);
    const float4* pd = (const float4*)(g_all + (size_t)d * 512);
    float sum = 0.f;
#pragma unroll
    for (int t = 0; t < 8; t++) {
        float4 a = __ldg(ps + lane + 16 * t);
        float4 b = __ldg(pd + lane + 16 * t);
        sum += a.x * b.x + a.y * b.y + a.z * b.z + a.w * b.w;
    }
#pragma unroll
    for (int off = 8; off > 0; off >>= 1)
        sum += __shfl_xor_sync(0xffffffffu, sum, off);
    if (lane == 0) out[q] = sum;
}

// ---------------- launch ----------------
extern "C" void kernel_launch(void* const* d_in, const int* in_sizes, int n_in,
                              void* d_out, int out_size) {
    const int*   ei  = (const int*)d_in[0];
    const int*   eli = (const int*)d_in[1];
    const float* wt  = (const float*)d_in[2];
    const float* emb = (const float*)d_in[3];
    const float* gcw = (const float*)d_in[4];
    const float* gcb = (const float*)d_in[5];
    const float* biw = (const float*)d_in[6];
    const float* bib = (const float*)d_in[7];

    int E = in_sizes[2];
    int Q = in_sizes[1] / 2;
    int N = in_sizes[3] / DIM;

    static bool attr_set = false;
    if (!attr_set) {
        cudaFuncSetAttribute(layer_kernel, cudaFuncAttributeMaxDynamicSharedMemorySize, LK_SMEM);
        attr_set = true;
    }

    prep_kernel<<<(3 * 128 * 256 + 255) / 256, 256>>>(gcw, gcb, biw, bib);
    init_kernel<<<(N * 32 + 255) / 256, 256>>>(emb, N);

    int nblk = (N + 1023) / 1024;
    csr_zero_kernel<<<256, 256>>>(N);
    csr_hist_kernel<<<1024, 256>>>(ei, E);
    csr_scan_local_kernel<<<nblk, 1024>>>(N);
    csr_scan_bsum_kernel<<<1, 256>>>(nblk);
    csr_scan_add_kernel<<<(N + 255) / 256, 256>>>(N, E);
    csr_fill_kernel<<<1024, 256>>>(ei, wt, E);

    int sel = 0;
    for (int i = 0; i < 3; i++) {
        long long gthreads = (long long)N * 32;
        int gblocks = (int)((gthreads + 255) / 256);
        gather_kernel<<<gblocks, 256>>>(sel, N);
        layer_kernel<<<(N + 127) / 128, 256, LK_SMEM>>>(sel, i, N);
        sel ^= 1;
    }
    score_kernel<<<(Q * 16 + 255) / 256, 256>>>(eli, (float*)d_out, Q);
}

// round 12
// speedup vs baseline: 1.3048x; 1.0144x over previous
#include <cuda_runtime.h>
#include <cuda_bf16.h>
#include <cstdint>

#define MAXN 100000
#define MAXE 1600000
#define DIM 128

// ---------------- device scratch (no allocations allowed) ----------------
__device__ float g_seg[(size_t)MAXN * DIM];        // current normalized segment (reused x4)
__device__ float g_ego[2][(size_t)MAXN * DIM];     // ping-pong ego buffers (unnormalized)
__device__ __nv_bfloat16 g_h_hi[(size_t)MAXN * 256];   // H=[msg|ego*msg] hi
__device__ __nv_bfloat16 g_h_lo[(size_t)MAXN * 256];   // H lo residual
__device__ __nv_bfloat16 g_wbf_hi[3 * 128 * 256];  // [layer][j][k] combined W rows, bf16 hi
__device__ __nv_bfloat16 g_wbf_lo[3 * 128 * 256];  // bf16 lo (residual)
__device__ float g_bias[3 * 128];                  // gc_b + bi_b
// CSR
__device__ int   g_deg[MAXN];
__device__ int   g_cur[MAXN];
__device__ int   g_off[MAXN + 1];
__device__ int   g_bsum[256];
__device__ int   g_ccol[MAXE];
__device__ float g_cw[MAXE];

// ================= helpers =================
__device__ __forceinline__ uint32_t smem_u32(const void* p) {
    uint32_t a;
    asm("{ .reg .u64 t; cvta.to.shared.u64 t, %1; cvt.u32.u64 %0, t; }" : "=r"(a) : "l"(p));
    return a;
}
#define LDSM_X4(r, addr) \
    asm volatile("ldmatrix.sync.aligned.m8n8.x4.shared.b16 {%0,%1,%2,%3}, [%4];" \
        : "=r"((r)[0]), "=r"((r)[1]), "=r"((r)[2]), "=r"((r)[3]) : "r"(addr))

__device__ __forceinline__ void mma16816(float* c, const uint32_t* a, const uint32_t* b) {
    asm volatile("mma.sync.aligned.m16n8k16.row.col.f32.bf16.bf16.f32 "
        "{%0,%1,%2,%3}, {%4,%5,%6,%7}, {%8,%9}, {%0,%1,%2,%3};"
        : "+f"(c[0]), "+f"(c[1]), "+f"(c[2]), "+f"(c[3])
        : "r"(a[0]), "r"(a[1]), "r"(a[2]), "r"(a[3]), "r"(b[0]), "r"(b[1]));
}
__device__ __forceinline__ void cp_async16(uint32_t smem, const void* g, uint32_t srcsize) {
    asm volatile("cp.async.cg.shared.global [%0], [%1], 16, %2;"
                 :: "r"(smem), "l"(g), "r"(srcsize) : "memory");
}
#define CP_COMMIT() asm volatile("cp.async.commit_group;" ::: "memory")
#define CP_WAIT1() asm volatile("cp.async.wait_group 1;" ::: "memory")
#define CP_WAIT0() asm volatile("cp.async.wait_group 0;" ::: "memory")

// ---------------- prep: combined W rows -> bf16 hi/lo, bias ----------------
__global__ void prep_kernel(const float* __restrict__ gcw, const float* __restrict__ gcb,
                            const float* __restrict__ biw, const float* __restrict__ bib) {
    int t = blockIdx.x * blockDim.x + threadIdx.x;
    if (t >= 3 * 128 * 256) return;
    int i = t >> 15;
    int r = t & 32767;
    int j = r >> 8, k = r & 255;
    float v;
    if (k < 128) v = gcw[i * 16384 + j * 128 + k];
    else         v = biw[i * 16384 + j * 128 + (k - 128)];
    __nv_bfloat16 hi = __float2bfloat16_rn(v);
    __nv_bfloat16 lo = __float2bfloat16_rn(v - __bfloat162float(hi));
    g_wbf_hi[t] = hi;
    g_wbf_lo[t] = lo;
    if (k == 0) g_bias[i * 128 + j] = gcb[i * 128 + j] + bib[i * 128 + j];
}

// ---------------- init: ego0 = emb ----------------
__global__ void init_kernel(const float* __restrict__ emb, int N) {
    int t = blockIdx.x * blockDim.x + threadIdx.x;
    int total = N * 32;
    if (t >= total) return;
    ((float4*)g_ego[0])[t] = ((const float4*)emb)[t];
}

// ---------------- CSR build ----------------
__global__ void csr_zero_kernel(int N) {
    for (int i = blockIdx.x * blockDim.x + threadIdx.x; i < N; i += gridDim.x * blockDim.x) {
        g_deg[i] = 0;
        g_cur[i] = 0;
    }
}
__global__ void csr_hist_kernel(const int* __restrict__ ei, int E) {
    for (int e = blockIdx.x * blockDim.x + threadIdx.x; e < E; e += gridDim.x * blockDim.x)
        atomicAdd(&g_deg[ei[e]], 1);
}
__global__ void csr_scan_local_kernel(int N) {
    __shared__ int sm[1024];
    int b = blockIdx.x, t = threadIdx.x;
    int i = b * 1024 + t;
    int v = (i < N) ? g_deg[i] : 0;
    sm[t] = v;
    __syncthreads();
#pragma unroll
    for (int off = 1; off < 1024; off <<= 1) {
        int x = sm[t];
        int y = (t >= off) ? sm[t - off] : 0;
        __syncthreads();
        sm[t] = x + y;
        __syncthreads();
    }
    if (i < N) g_off[i] = sm[t] - v;
    if (t == 1023) g_bsum[b] = sm[t];
}
__global__ void csr_scan_bsum_kernel(int nblk) {
    __shared__ int sm[256];
    int t = threadIdx.x;
    int v = (t < nblk) ? g_bsum[t] : 0;
    sm[t] = v;
    __syncthreads();
#pragma unroll
    for (int off = 1; off < 256; off <<= 1) {
        int x = sm[t];
        int y = (t >= off) ? sm[t - off] : 0;
        __syncthreads();
        sm[t] = x + y;
        __syncthreads();
    }
    g_bsum[t] = sm[t] - v;
}
__global__ void csr_scan_add_kernel(int N, int E) {
    int i = blockIdx.x * blockDim.x + threadIdx.x;
    if (i < N) g_off[i] += g_bsum[i >> 10];
    if (i == 0) g_off[N] = E;
}
__global__ void csr_fill_kernel(const int* __restrict__ ei, const float* __restrict__ wt, int E) {
    for (int e = blockIdx.x * blockDim.x + threadIdx.x; e < E; e += gridDim.x * blockDim.x) {
        int row = ei[e];
        int pos = g_off[row] + atomicAdd(&g_cur[row], 1);
        g_ccol[pos] = ei[E + e];
        g_cw[pos] = wt[e];
    }
}

// ---------------- gather: msg = A@ego, then emit H=[msg|ego*msg] split-bf16 ----------------
__device__ __forceinline__ void split_pair(float x, float y, uint32_t& hi, uint32_t& lo) {
    __nv_bfloat162 h = __floats2bfloat162_rn(x, y);
    __nv_bfloat162 l = __floats2bfloat162_rn(x - __bfloat162float(h.x), y - __bfloat162float(h.y));
    hi = *reinterpret_cast<uint32_t*>(&h);
    lo = *reinterpret_cast<uint32_t*>(&l);
}

__global__ void gather_kernel(int sel, int N) {
    int g = blockIdx.x * blockDim.x + threadIdx.x;
    int n = g >> 5;
    if (n >= N) return;
    int lane = g & 31;
    int s = g_off[n], e = g_off[n + 1];
    const float* __restrict__ ego = g_ego[sel];
    float4 acc = make_float4(0.f, 0.f, 0.f, 0.f);
    int i = s;
    for (; i + 4 <= e; i += 4) {
        int c0 = __ldg(g_ccol + i), c1 = __ldg(g_ccol + i + 1);
        int c2 = __ldg(g_ccol + i + 2), c3 = __ldg(g_ccol + i + 3);
        float w0 = __ldg(g_cw + i), w1 = __ldg(g_cw + i + 1);
        float w2 = __ldg(g_cw + i + 2), w3 = __ldg(g_cw + i + 3);
        float4 v0 = __ldg((const float4*)(ego + (size_t)c0 * DIM) + lane);
        float4 v1 = __ldg((const float4*)(ego + (size_t)c1 * DIM) + lane);
        float4 v2 = __ldg((const float4*)(ego + (size_t)c2 * DIM) + lane);
        float4 v3 = __ldg((const float4*)(ego + (size_t)c3 * DIM) + lane);
        acc.x += w0 * v0.x; acc.y += w0 * v0.y; acc.z += w0 * v0.z; acc.w += w0 * v0.w;
        acc.x += w1 * v1.x; acc.y += w1 * v1.y; acc.z += w1 * v1.z; acc.w += w1 * v1.w;
        acc.x += w2 * v2.x; acc.y += w2 * v2.y; acc.z += w2 * v2.z; acc.w += w2 * v2.w;
        acc.x += w3 * v3.x; acc.y += w3 * v3.y; acc.z += w3 * v3.z; acc.w += w3 * v3.w;
    }
    for (; i < e; i++) {
        int c = __ldg(g_ccol + i);
        float w = __ldg(g_cw + i);
        float4 v = __ldg((const float4*)(ego + (size_t)c * DIM) + lane);
        acc.x += w * v.x; acc.y += w * v.y; acc.z += w * v.z; acc.w += w * v.w;
    }
    // own ego row (coalesced)
    float4 eg = __ldg((const float4*)(ego + (size_t)n * DIM) + lane);
    float4 pr = make_float4(acc.x * eg.x, acc.y * eg.y, acc.z * eg.z, acc.w * eg.w);

    char* hi_row = (char*)(g_h_hi + (size_t)n * 256);
    char* lo_row = (char*)(g_h_lo + (size_t)n * 256);
    uint2 mh, ml, ph, pl;
    split_pair(acc.x, acc.y, mh.x, ml.x);
    split_pair(acc.z, acc.w, mh.y, ml.y);
    split_pair(pr.x, pr.y, ph.x, pl.x);
    split_pair(pr.z, pr.w, ph.y, pl.y);
    *(uint2*)(hi_row + lane * 8) = mh;
    *(uint2*)(lo_row + lane * 8) = ml;
    *(uint2*)(hi_row + 256 + lane * 8) = ph;
    *(uint2*)(lo_row + 256 + lane * 8) = pl;
}

// ================= layer GEMM: pipelined cp.async + mma.sync (bf16x3) =================
// Block 128x128, K=256 in 4 stages of 64. 256 threads, 8 warps, warp tile 64x32.
#define SMEM_B_HI 0          // 65536
#define SMEM_B_LO 65536      // 65536
#define SMEM_A    131072     // 2 stages x (Ahi 16KB + Alo 16KB)
#define LK_SMEM   196608
#define EPI_ROWPART 69632    // float [128][4]  (reuses B region post-MMA)
#define EPI_SCALE   71680    // float [128]

__device__ __forceinline__ void issue_a_stage(char* smem, int kb, int buf, int n0, int N, int tid) {
    uint32_t abase = smem_u32(smem + SMEM_A + buf * 32768);
    const char* hsrc = (const char*)g_h_hi;
    const char* lsrc = (const char*)g_h_lo;
#pragma unroll
    for (int it = 0; it < 4; it++) {
        int idx = tid + 256 * it;           // 1024 chunks
        int row = idx >> 3, c = idx & 7;
        int n = n0 + row;
        uint32_t sz = (n < N) ? 16u : 0u;
        size_t so = (size_t)(n < N ? n : 0) * 512 + kb * 128 + c * 16;
        uint32_t ci = (uint32_t)(row * 8 + (c ^ (row & 7))) * 16;
        cp_async16(abase + ci, hsrc + so, sz);
        cp_async16(abase + 16384 + ci, lsrc + so, sz);
    }
}

__global__ __launch_bounds__(256, 1) void layer_kernel(int sel, int layer, int N) {
    extern __shared__ char smem[];
    const uint32_t sb = smem_u32(smem);
    const int tid = threadIdx.x;
    const int wid = tid >> 5;
    const int lid = tid & 31;
    const int n0 = blockIdx.x * 128;
    const int wm = wid >> 2;
    const int wn = wid & 3;

    // ---- resident B (full layer W, hi+lo, 128KB) + A stages ----
    {
        const char* wh = (const char*)(g_wbf_hi) + (size_t)layer * 65536;
        const char* wl = (const char*)(g_wbf_lo) + (size_t)layer * 65536;
        uint32_t bh = sb + SMEM_B_HI, bl = sb + SMEM_B_LO;
#pragma unroll
        for (int it = 0; it < 16; it++) {
            int idx = tid + 256 * it;       // 4096 chunks: [kb 4][row 128][c 8]
            int kb = idx >> 10;
            int r = (idx >> 3) & 127;
            int c = idx & 7;
            size_t so = (size_t)r * 512 + kb * 128 + c * 16;
            uint32_t ci = (uint32_t)(kb * 16384) + (uint32_t)(r * 8 + (c ^ (r & 7))) * 16;
            cp_async16(bh + ci, wh + so, 16);
            cp_async16(bl + ci, wl + so, 16);
        }
    }
    issue_a_stage(smem, 0, 0, n0, N, tid);
    CP_COMMIT();
    issue_a_stage(smem, 1, 1, n0, N, tid);
    CP_COMMIT();

    float acc[4][4][4];
#pragma unroll
    for (int mt = 0; mt < 4; mt++)
#pragma unroll
        for (int nt = 0; nt < 4; nt++)
#pragma unroll
            for (int c = 0; c < 4; c++) acc[mt][nt][c] = 0.f;

#pragma unroll
    for (int kb = 0; kb < 4; kb++) {
        if (kb < 3) CP_WAIT1(); else CP_WAIT0();
        __syncthreads();

        uint32_t abase = sb + SMEM_A + (kb & 1) * 32768;
        uint32_t bhbase = sb + SMEM_B_HI + kb * 16384;
        uint32_t blbase = sb + SMEM_B_LO + kb * 16384;
#pragma unroll
        for (int ks = 0; ks < 4; ks++) {
            uint32_t ahi[4][4], alo[4][4];
            int lr = lid & 15, lk = lid >> 4;
#pragma unroll
            for (int mt = 0; mt < 4; mt++) {
                int r = wm * 64 + mt * 16 + lr;
                int kc = ks * 2 + lk;
                uint32_t off = (uint32_t)(r * 8 + (kc ^ (r & 7))) * 16;
                LDSM_X4(ahi[mt], abase + off);
                LDSM_X4(alo[mt], abase + 16384 + off);
            }
            uint32_t bhi[2][4], blo[2][4];
            int nr = (lid & 7) + ((lid >> 4) << 3);
            int nk = (lid >> 3) & 1;
#pragma unroll
            for (int np = 0; np < 2; np++) {
                int r = wn * 32 + np * 16 + nr;
                int kc = ks * 2 + nk;
                uint32_t off = (uint32_t)(r * 8 + (kc ^ (r & 7))) * 16;
                LDSM_X4(bhi[np], bhbase + off);
                LDSM_X4(blo[np], blbase + off);
            }
#pragma unroll
            for (int mt = 0; mt < 4; mt++)
#pragma unroll
                for (int nt = 0; nt < 4; nt++) {
                    const uint32_t* bh = &bhi[nt >> 1][(nt & 1) * 2];
                    const uint32_t* bl = &blo[nt >> 1][(nt & 1) * 2];
                    mma16816(acc[mt][nt], ahi[mt], bh);
                    mma16816(acc[mt][nt], ahi[mt], bl);
                    mma16816(acc[mt][nt], alo[mt], bh);
                }
        }
        __syncthreads();
        if (kb + 2 < 4) { issue_a_stage(smem, kb + 2, kb & 1, n0, N, tid); CP_COMMIT(); }
    }

    // ================= epilogue (reuses B SMEM region) =================
    float* stage = (float*)smem;                      // [128][136]
    float* rowpart = (float*)(smem + EPI_ROWPART);    // [128][4]
    const float* bias = g_bias + layer * 128;
    int qid = lid >> 2, qt = lid & 3;
#pragma unroll
    for (int mt = 0; mt < 4; mt++) {
        int rA = wm * 64 + mt * 16 + qid;
        int rB = rA + 8;
        float sqa = 0.f, sqb = 0.f;
#pragma unroll
        for (int nt = 0; nt < 4; nt++) {
            int col = wn * 32 + nt * 8 + 2 * qt;
            float b0 = __ldg(bias + col), b1 = __ldg(bias + col + 1);
            float* c = acc[mt][nt];
            float x0 = c[0] + b0, x1 = c[1] + b1;
            float y0 = c[2] + b0, y1 = c[3] + b1;
            x0 = x0 > 0.f ? x0 : 0.2f * x0;
            x1 = x1 > 0.f ? x1 : 0.2f * x1;
            y0 = y0 > 0.f ? y0 : 0.2f * y0;
            y1 = y1 > 0.f ? y1 : 0.2f * y1;
            stage[rA * 136 + col] = x0;
            stage[rA * 136 + col + 1] = x1;
            stage[rB * 136 + col] = y0;
            stage[rB * 136 + col + 1] = y1;
            sqa += x0 * x0 + x1 * x1;
            sqb += y0 * y0 + y1 * y1;
        }
        sqa += __shfl_xor_sync(0xffffffffu, sqa, 1);
        sqa += __shfl_xor_sync(0xffffffffu, sqa, 2);
        sqb += __shfl_xor_sync(0xffffffffu, sqb, 1);
        sqb += __shfl_xor_sync(0xffffffffu, sqb, 2);
        if (qt == 0) {
            rowpart[rA * 4 + wn] = sqa;
            rowpart[rB * 4 + wn] = sqb;
        }
    }
    __syncthreads();
    float* scl = (float*)(smem + EPI_SCALE);
    if (tid < 128) {
        float tot = rowpart[tid * 4] + rowpart[tid * 4 + 1] + rowpart[tid * 4 + 2] + rowpart[tid * 4 + 3];
        scl[tid] = 1.0f / fmaxf(sqrtf(tot), 1e-12f);
    }
    __syncthreads();
    float* ego_out = g_ego[sel ^ 1];
#pragma unroll
    for (int it = 0; it < 16; it++) {
        int idx = tid + 256 * it;
        int r = idx >> 5, j = idx & 31;
        int n = n0 + r;
        if (n < N) {
            float4 v = *(const float4*)(stage + r * 136 + j * 4);
            ((float4*)(ego_out + (size_t)n * DIM))[j] = v;
            float s = scl[r];
            float4 sv = make_float4(v.x * s, v.y * s, v.z * s, v.w * s);
            ((float4*)(g_seg + (size_t)n * DIM))[j] = sv;
        }
    }
}

// ---------------- segment scoring: out[q] (+)= dot(row[s], row[d]) over 128 ----------------
// use_emb=1: read from the emb input pointer; else read from g_seg device buffer.
// 8 lanes per query (4 queries/warp).
__global__ void score_seg_kernel(const int* __restrict__ eli, const float* __restrict__ emb,
                                 float* __restrict__ out, int Q, int use_emb, int add) {
    int g = blockIdx.x * blockDim.x + threadIdx.x;
    int q = g >> 3;
    if (q >= Q) return;
    int lane = g & 7;
    int s = __ldg(eli + q);
    int d = __ldg(eli + Q + q);
    const float* base = use_emb ? emb : (const float*)g_seg;
    const float4* ps = (const float4*)(base + (size_t)s * DIM);
    const float4* pd = (const float4*)(base + (size_t)d * DIM);
    float sum = 0.f;
#pragma unroll
    for (int t = 0; t < 4; t++) {
        float4 a = __ldg(ps + lane + 8 * t);
        float4 b = __ldg(pd + lane + 8 * t);
        sum += a.x * b.x + a.y * b.y + a.z * b.z + a.w * b.w;
    }
    sum += __shfl_xor_sync(0xffffffffu, sum, 1);
    sum += __shfl_xor_sync(0xffffffffu, sum, 2);
    sum += __shfl_xor_sync(0xffffffffu, sum, 4);
    if (lane == 0) {
        if (add) out[q] += sum;
        else     out[q] = sum;
    }
}

// ---------------- launch ----------------
extern "C" void kernel_launch(void* const* d_in, const int* in_sizes, int n_in,
                              void* d_out, int out_size) {
    const int*   ei  = (const int*)d_in[0];
    const int*   eli = (const int*)d_in[1];
    const float* wt  = (const float*)d_in[2];
    const float* emb = (const float*)d_in[3];
    const float* gcw = (const float*)d_in[4];
    const float* gcb = (const float*)d_in[5];
    const float* biw = (const float*)d_in[6];
    const float* bib = (const float*)d_in[7];

    int E = in_sizes[2];
    int Q = in_sizes[1] / 2;
    int N = in_sizes[3] / DIM;

    static bool attr_set = false;
    if (!attr_set) {
        cudaFuncSetAttribute(layer_kernel, cudaFuncAttributeMaxDynamicSharedMemorySize, LK_SMEM);
        attr_set = true;
    }

    prep_kernel<<<(3 * 128 * 256 + 255) / 256, 256>>>(gcw, gcb, biw, bib);
    init_kernel<<<(N * 32 + 255) / 256, 256>>>(emb, N);

    int nblk = (N + 1023) / 1024;
    csr_zero_kernel<<<256, 256>>>(N);
    csr_hist_kernel<<<1024, 256>>>(ei, E);
    csr_scan_local_kernel<<<nblk, 1024>>>(N);
    csr_scan_bsum_kernel<<<1, 256>>>(nblk);
    csr_scan_add_kernel<<<(N + 255) / 256, 256>>>(N, E);
    csr_fill_kernel<<<1024, 256>>>(ei, wt, E);

    int sblocks = (int)(((long long)Q * 8 + 255) / 256);
    // segment 0: raw embeddings
    score_seg_kernel<<<sblocks, 256>>>(eli, emb, (float*)d_out, Q, 1, 0);

    int sel = 0;
    for (int i = 0; i < 3; i++) {
        long long gthreads = (long long)N * 32;
        int gblocks = (int)((gthreads + 255) / 256);
        gather_kernel<<<gblocks, 256>>>(sel, N);
        layer_kernel<<<(N + 127) / 128, 256, LK_SMEM>>>(sel, i, N);
        score_seg_kernel<<<sblocks, 256>>>(eli, emb, (float*)d_out, Q, 0, 1);
        sel ^= 1;
    }
}

// round 13
// speedup vs baseline: 1.3840x; 1.0607x over previous
#include <cuda_runtime.h>
#include <cuda_bf16.h>
#include <cstdint>

#define MAXN 100000
#define MAXE 1600000
#define DIM 128

// ---------------- device scratch (no allocations allowed) ----------------
__device__ float g_seg[(size_t)MAXN * DIM];        // current normalized segment (reused x4)
__device__ float g_ego[2][(size_t)MAXN * DIM];     // ping-pong ego buffers (unnormalized)
__device__ __nv_bfloat16 g_h_hi[(size_t)MAXN * 256];   // H=[msg|ego*msg] hi
__device__ __nv_bfloat16 g_h_lo[(size_t)MAXN * 256];   // H lo residual
__device__ __nv_bfloat16 g_wbf_hi[3 * 128 * 256];  // [layer][j][k] combined W rows, bf16 hi
__device__ __nv_bfloat16 g_wbf_lo[3 * 128 * 256];  // bf16 lo (residual)
__device__ float g_bias[3 * 128];                  // gc_b + bi_b
// CSR
__device__ int   g_deg[MAXN];
__device__ int   g_cur[MAXN];
__device__ int   g_off[MAXN + 1];
__device__ int   g_bsum[256];
__device__ int   g_ccol[MAXE];
__device__ float g_cw[MAXE];

// ================= helpers =================
__device__ __forceinline__ uint32_t smem_u32(const void* p) {
    uint32_t a;
    asm("{ .reg .u64 t; cvta.to.shared.u64 t, %1; cvt.u32.u64 %0, t; }" : "=r"(a) : "l"(p));
    return a;
}
#define LDSM_X4(r, addr) \
    asm volatile("ldmatrix.sync.aligned.m8n8.x4.shared.b16 {%0,%1,%2,%3}, [%4];" \
        : "=r"((r)[0]), "=r"((r)[1]), "=r"((r)[2]), "=r"((r)[3]) : "r"(addr))

__device__ __forceinline__ void mma16816(float* c, const uint32_t* a, const uint32_t* b) {
    asm volatile("mma.sync.aligned.m16n8k16.row.col.f32.bf16.bf16.f32 "
        "{%0,%1,%2,%3}, {%4,%5,%6,%7}, {%8,%9}, {%0,%1,%2,%3};"
        : "+f"(c[0]), "+f"(c[1]), "+f"(c[2]), "+f"(c[3])
        : "r"(a[0]), "r"(a[1]), "r"(a[2]), "r"(a[3]), "r"(b[0]), "r"(b[1]));
}
__device__ __forceinline__ void cp_async16(uint32_t smem, const void* g, uint32_t srcsize) {
    asm volatile("cp.async.cg.shared.global [%0], [%1], 16, %2;"
                 :: "r"(smem), "l"(g), "r"(srcsize) : "memory");
}
#define CP_COMMIT() asm volatile("cp.async.commit_group;" ::: "memory")
#define CP_WAIT1() asm volatile("cp.async.wait_group 1;" ::: "memory")
#define CP_WAIT0() asm volatile("cp.async.wait_group 0;" ::: "memory")

// ---------------- prep: combined W rows -> bf16 hi/lo, bias ----------------
__global__ void prep_kernel(const float* __restrict__ gcw, const float* __restrict__ gcb,
                            const float* __restrict__ biw, const float* __restrict__ bib) {
    int t = blockIdx.x * blockDim.x + threadIdx.x;
    if (t >= 3 * 128 * 256) return;
    int i = t >> 15;
    int r = t & 32767;
    int j = r >> 8, k = r & 255;
    float v;
    if (k < 128) v = gcw[i * 16384 + j * 128 + k];
    else         v = biw[i * 16384 + j * 128 + (k - 128)];
    __nv_bfloat16 hi = __float2bfloat16_rn(v);
    __nv_bfloat16 lo = __float2bfloat16_rn(v - __bfloat162float(hi));
    g_wbf_hi[t] = hi;
    g_wbf_lo[t] = lo;
    if (k == 0) g_bias[i * 128 + j] = gcb[i * 128 + j] + bib[i * 128 + j];
}

// ---------------- CSR build ----------------
__global__ void csr_zero_kernel(int N) {
    for (int i = blockIdx.x * blockDim.x + threadIdx.x; i < N; i += gridDim.x * blockDim.x) {
        g_deg[i] = 0;
        g_cur[i] = 0;
    }
}
__global__ void csr_hist_kernel(const int* __restrict__ ei, int E) {
    for (int e = blockIdx.x * blockDim.x + threadIdx.x; e < E; e += gridDim.x * blockDim.x)
        atomicAdd(&g_deg[ei[e]], 1);
}
__global__ void csr_scan_local_kernel(int N) {
    __shared__ int sm[1024];
    int b = blockIdx.x, t = threadIdx.x;
    int i = b * 1024 + t;
    int v = (i < N) ? g_deg[i] : 0;
    sm[t] = v;
    __syncthreads();
#pragma unroll
    for (int off = 1; off < 1024; off <<= 1) {
        int x = sm[t];
        int y = (t >= off) ? sm[t - off] : 0;
        __syncthreads();
        sm[t] = x + y;
        __syncthreads();
    }
    if (i < N) g_off[i] = sm[t] - v;
    if (t == 1023) g_bsum[b] = sm[t];
}
__global__ void csr_scan_bsum_kernel(int nblk) {
    __shared__ int sm[256];
    int t = threadIdx.x;
    int v = (t < nblk) ? g_bsum[t] : 0;
    sm[t] = v;
    __syncthreads();
#pragma unroll
    for (int off = 1; off < 256; off <<= 1) {
        int x = sm[t];
        int y = (t >= off) ? sm[t - off] : 0;
        __syncthreads();
        sm[t] = x + y;
        __syncthreads();
    }
    g_bsum[t] = sm[t] - v;
}
__global__ void csr_scan_add_kernel(int N, int E) {
    int i = blockIdx.x * blockDim.x + threadIdx.x;
    if (i < N) g_off[i] += g_bsum[i >> 10];
    if (i == 0) g_off[N] = E;
}
__global__ void csr_fill_kernel(const int* __restrict__ ei, const float* __restrict__ wt, int E) {
    for (int e = blockIdx.x * blockDim.x + threadIdx.x; e < E; e += gridDim.x * blockDim.x) {
        int row = ei[e];
        int pos = g_off[row] + atomicAdd(&g_cur[row], 1);
        g_ccol[pos] = ei[E + e];
        g_cw[pos] = wt[e];
    }
}

// ---------------- gather: msg = A@ego, then emit H=[msg|ego*msg] split-bf16 ----------------
__device__ __forceinline__ void split_pair(float x, float y, uint32_t& hi, uint32_t& lo) {
    __nv_bfloat162 h = __floats2bfloat162_rn(x, y);
    __nv_bfloat162 l = __floats2bfloat162_rn(x - __bfloat162float(h.x), y - __bfloat162float(h.y));
    hi = *reinterpret_cast<uint32_t*>(&h);
    lo = *reinterpret_cast<uint32_t*>(&l);
}

__global__ void gather_kernel(const float* __restrict__ emb, int use_emb, int sel, int N) {
    int g = blockIdx.x * blockDim.x + threadIdx.x;
    int n = g >> 5;
    if (n >= N) return;
    int lane = g & 31;
    int s = g_off[n], e = g_off[n + 1];
    const float* __restrict__ ego = use_emb ? emb : g_ego[sel];
    float4 acc = make_float4(0.f, 0.f, 0.f, 0.f);
    int i = s;
    for (; i + 4 <= e; i += 4) {
        int c0 = __ldg(g_ccol + i), c1 = __ldg(g_ccol + i + 1);
        int c2 = __ldg(g_ccol + i + 2), c3 = __ldg(g_ccol + i + 3);
        float w0 = __ldg(g_cw + i), w1 = __ldg(g_cw + i + 1);
        float w2 = __ldg(g_cw + i + 2), w3 = __ldg(g_cw + i + 3);
        float4 v0 = __ldg((const float4*)(ego + (size_t)c0 * DIM) + lane);
        float4 v1 = __ldg((const float4*)(ego + (size_t)c1 * DIM) + lane);
        float4 v2 = __ldg((const float4*)(ego + (size_t)c2 * DIM) + lane);
        float4 v3 = __ldg((const float4*)(ego + (size_t)c3 * DIM) + lane);
        acc.x += w0 * v0.x; acc.y += w0 * v0.y; acc.z += w0 * v0.z; acc.w += w0 * v0.w;
        acc.x += w1 * v1.x; acc.y += w1 * v1.y; acc.z += w1 * v1.z; acc.w += w1 * v1.w;
        acc.x += w2 * v2.x; acc.y += w2 * v2.y; acc.z += w2 * v2.z; acc.w += w2 * v2.w;
        acc.x += w3 * v3.x; acc.y += w3 * v3.y; acc.z += w3 * v3.z; acc.w += w3 * v3.w;
    }
    for (; i < e; i++) {
        int c = __ldg(g_ccol + i);
        float w = __ldg(g_cw + i);
        float4 v = __ldg((const float4*)(ego + (size_t)c * DIM) + lane);
        acc.x += w * v.x; acc.y += w * v.y; acc.z += w * v.z; acc.w += w * v.w;
    }
    // own ego row (coalesced)
    float4 eg = __ldg((const float4*)(ego + (size_t)n * DIM) + lane);
    float4 pr = make_float4(acc.x * eg.x, acc.y * eg.y, acc.z * eg.z, acc.w * eg.w);

    char* hi_row = (char*)(g_h_hi + (size_t)n * 256);
    char* lo_row = (char*)(g_h_lo + (size_t)n * 256);
    uint2 mh, ml, ph, pl;
    split_pair(acc.x, acc.y, mh.x, ml.x);
    split_pair(acc.z, acc.w, mh.y, ml.y);
    split_pair(pr.x, pr.y, ph.x, pl.x);
    split_pair(pr.z, pr.w, ph.y, pl.y);
    *(uint2*)(hi_row + lane * 8) = mh;
    *(uint2*)(lo_row + lane * 8) = ml;
    *(uint2*)(hi_row + 256 + lane * 8) = ph;
    *(uint2*)(lo_row + 256 + lane * 8) = pl;
}

// ================= layer GEMM: pipelined cp.async + mma.sync (bf16x3) =================
// Block 128x128, K=256 in 4 stages of 64. 256 threads, 8 warps, warp tile 64x32.
#define SMEM_B_HI 0          // 65536
#define SMEM_B_LO 65536      // 65536
#define SMEM_A    131072     // 2 stages x (Ahi 16KB + Alo 16KB)
#define LK_SMEM   196608
#define EPI_ROWPART 69632    // float [128][4]  (reuses B region post-MMA)
#define EPI_SCALE   71680    // float [128]

__device__ __forceinline__ void issue_a_stage(char* smem, int kb, int buf, int n0, int N, int tid) {
    uint32_t abase = smem_u32(smem + SMEM_A + buf * 32768);
    const char* hsrc = (const char*)g_h_hi;
    const char* lsrc = (const char*)g_h_lo;
#pragma unroll
    for (int it = 0; it < 4; it++) {
        int idx = tid + 256 * it;           // 1024 chunks
        int row = idx >> 3, c = idx & 7;
        int n = n0 + row;
        uint32_t sz = (n < N) ? 16u : 0u;
        size_t so = (size_t)(n < N ? n : 0) * 512 + kb * 128 + c * 16;
        uint32_t ci = (uint32_t)(row * 8 + (c ^ (row & 7))) * 16;
        cp_async16(abase + ci, hsrc + so, sz);
        cp_async16(abase + 16384 + ci, lsrc + so, sz);
    }
}

__global__ __launch_bounds__(256, 1) void layer_kernel(int outsel, int layer, int N, int write_ego) {
    extern __shared__ char smem[];
    const uint32_t sb = smem_u32(smem);
    const int tid = threadIdx.x;
    const int wid = tid >> 5;
    const int lid = tid & 31;
    const int n0 = blockIdx.x * 128;
    const int wm = wid >> 2;
    const int wn = wid & 3;

    // ---- resident B (full layer W, hi+lo, 128KB) + A stages ----
    {
        const char* wh = (const char*)(g_wbf_hi) + (size_t)layer * 65536;
        const char* wl = (const char*)(g_wbf_lo) + (size_t)layer * 65536;
        uint32_t bh = sb + SMEM_B_HI, bl = sb + SMEM_B_LO;
#pragma unroll
        for (int it = 0; it < 16; it++) {
            int idx = tid + 256 * it;       // 4096 chunks: [kb 4][row 128][c 8]
            int kb = idx >> 10;
            int r = (idx >> 3) & 127;
            int c = idx & 7;
            size_t so = (size_t)r * 512 + kb * 128 + c * 16;
            uint32_t ci = (uint32_t)(kb * 16384) + (uint32_t)(r * 8 + (c ^ (r & 7))) * 16;
            cp_async16(bh + ci, wh + so, 16);
            cp_async16(bl + ci, wl + so, 16);
        }
    }
    issue_a_stage(smem, 0, 0, n0, N, tid);
    CP_COMMIT();
    issue_a_stage(smem, 1, 1, n0, N, tid);
    CP_COMMIT();

    float acc[4][4][4];
#pragma unroll
    for (int mt = 0; mt < 4; mt++)
#pragma unroll
        for (int nt = 0; nt < 4; nt++)
#pragma unroll
            for (int c = 0; c < 4; c++) acc[mt][nt][c] = 0.f;

#pragma unroll
    for (int kb = 0; kb < 4; kb++) {
        if (kb < 3) CP_WAIT1(); else CP_WAIT0();
        __syncthreads();

        uint32_t abase = sb + SMEM_A + (kb & 1) * 32768;
        uint32_t bhbase = sb + SMEM_B_HI + kb * 16384;
        uint32_t blbase = sb + SMEM_B_LO + kb * 16384;
#pragma unroll
        for (int ks = 0; ks < 4; ks++) {
            uint32_t ahi[4][4], alo[4][4];
            int lr = lid & 15, lk = lid >> 4;
#pragma unroll
            for (int mt = 0; mt < 4; mt++) {
                int r = wm * 64 + mt * 16 + lr;
                int kc = ks * 2 + lk;
                uint32_t off = (uint32_t)(r * 8 + (kc ^ (r & 7))) * 16;
                LDSM_X4(ahi[mt], abase + off);
                LDSM_X4(alo[mt], abase + 16384 + off);
            }
            uint32_t bhi[2][4], blo[2][4];
            int nr = (lid & 7) + ((lid >> 4) << 3);
            int nk = (lid >> 3) & 1;
#pragma unroll
            for (int np = 0; np < 2; np++) {
                int r = wn * 32 + np * 16 + nr;
                int kc = ks * 2 + nk;
                uint32_t off = (uint32_t)(r * 8 + (kc ^ (r & 7))) * 16;
                LDSM_X4(bhi[np], bhbase + off);
                LDSM_X4(blo[np], blbase + off);
            }
#pragma unroll
            for (int mt = 0; mt < 4; mt++)
#pragma unroll
                for (int nt = 0; nt < 4; nt++) {
                    const uint32_t* bh = &bhi[nt >> 1][(nt & 1) * 2];
                    const uint32_t* bl = &blo[nt >> 1][(nt & 1) * 2];
                    mma16816(acc[mt][nt], ahi[mt], bh);
                    mma16816(acc[mt][nt], ahi[mt], bl);
                    mma16816(acc[mt][nt], alo[mt], bh);
                }
        }
        __syncthreads();
        if (kb + 2 < 4) { issue_a_stage(smem, kb + 2, kb & 1, n0, N, tid); CP_COMMIT(); }
    }

    // ================= epilogue (reuses B SMEM region) =================
    float* stage = (float*)smem;                      // [128][136]
    float* rowpart = (float*)(smem + EPI_ROWPART);    // [128][4]
    const float* bias = g_bias + layer * 128;
    int qid = lid >> 2, qt = lid & 3;
#pragma unroll
    for (int mt = 0; mt < 4; mt++) {
        int rA = wm * 64 + mt * 16 + qid;
        int rB = rA + 8;
        float sqa = 0.f, sqb = 0.f;
#pragma unroll
        for (int nt = 0; nt < 4; nt++) {
            int col = wn * 32 + nt * 8 + 2 * qt;
            float b0 = __ldg(bias + col), b1 = __ldg(bias + col + 1);
            float* c = acc[mt][nt];
            float x0 = c[0] + b0, x1 = c[1] + b1;
            float y0 = c[2] + b0, y1 = c[3] + b1;
            x0 = x0 > 0.f ? x0 : 0.2f * x0;
            x1 = x1 > 0.f ? x1 : 0.2f * x1;
            y0 = y0 > 0.f ? y0 : 0.2f * y0;
            y1 = y1 > 0.f ? y1 : 0.2f * y1;
            stage[rA * 136 + col] = x0;
            stage[rA * 136 + col + 1] = x1;
            stage[rB * 136 + col] = y0;
            stage[rB * 136 + col + 1] = y1;
            sqa += x0 * x0 + x1 * x1;
            sqb += y0 * y0 + y1 * y1;
        }
        sqa += __shfl_xor_sync(0xffffffffu, sqa, 1);
        sqa += __shfl_xor_sync(0xffffffffu, sqa, 2);
        sqb += __shfl_xor_sync(0xffffffffu, sqb, 1);
        sqb += __shfl_xor_sync(0xffffffffu, sqb, 2);
        if (qt == 0) {
            rowpart[rA * 4 + wn] = sqa;
            rowpart[rB * 4 + wn] = sqb;
        }
    }
    __syncthreads();
    float* scl = (float*)(smem + EPI_SCALE);
    if (tid < 128) {
        float tot = rowpart[tid * 4] + rowpart[tid * 4 + 1] + rowpart[tid * 4 + 2] + rowpart[tid * 4 + 3];
        scl[tid] = 1.0f / fmaxf(sqrtf(tot), 1e-12f);
    }
    __syncthreads();
    float* ego_out = g_ego[outsel];
#pragma unroll
    for (int it = 0; it < 16; it++) {
        int idx = tid + 256 * it;
        int r = idx >> 5, j = idx & 31;
        int n = n0 + r;
        if (n < N) {
            float4 v = *(const float4*)(stage + r * 136 + j * 4);
            if (write_ego) ((float4*)(ego_out + (size_t)n * DIM))[j] = v;
            float s = scl[r];
            float4 sv = make_float4(v.x * s, v.y * s, v.z * s, v.w * s);
            ((float4*)(g_seg + (size_t)n * DIM))[j] = sv;
        }
    }
}

// ---------------- segment scoring: out[q] (+)= dot(row[s], row[d]) over 128 ----------------
__global__ void score_seg_kernel(const int* __restrict__ eli, const float* __restrict__ emb,
                                 float* __restrict__ out, int Q, int use_emb, int add) {
    int g = blockIdx.x * blockDim.x + threadIdx.x;
    int q = g >> 3;
    if (q >= Q) return;
    int lane = g & 7;
    int s = __ldg(eli + q);
    int d = __ldg(eli + Q + q);
    const float* base = use_emb ? emb : (const float*)g_seg;
    const float4* ps = (const float4*)(base + (size_t)s * DIM);
    const float4* pd = (const float4*)(base + (size_t)d * DIM);
    float sum = 0.f;
#pragma unroll
    for (int t = 0; t < 4; t++) {
        float4 a = __ldg(ps + lane + 8 * t);
        float4 b = __ldg(pd + lane + 8 * t);
        sum += a.x * b.x + a.y * b.y + a.z * b.z + a.w * b.w;
    }
    sum += __shfl_xor_sync(0xffffffffu, sum, 1);
    sum += __shfl_xor_sync(0xffffffffu, sum, 2);
    sum += __shfl_xor_sync(0xffffffffu, sum, 4);
    if (lane == 0) {
        if (add) out[q] += sum;
        else     out[q] = sum;
    }
}

// ---------------- launch ----------------
extern "C" void kernel_launch(void* const* d_in, const int* in_sizes, int n_in,
                              void* d_out, int out_size) {
    const int*   ei  = (const int*)d_in[0];
    const int*   eli = (const int*)d_in[1];
    const float* wt  = (const float*)d_in[2];
    const float* emb = (const float*)d_in[3];
    const float* gcw = (const float*)d_in[4];
    const float* gcb = (const float*)d_in[5];
    const float* biw = (const float*)d_in[6];
    const float* bib = (const float*)d_in[7];

    int E = in_sizes[2];
    int Q = in_sizes[1] / 2;
    int N = in_sizes[3] / DIM;

    static bool inited = false;
    static cudaStream_t s1;
    static cudaEvent_t evFork, evCsr, evScore[3], evJoin;
    if (!inited) {
        cudaFuncSetAttribute(layer_kernel, cudaFuncAttributeMaxDynamicSharedMemorySize, LK_SMEM);
        cudaStreamCreateWithFlags(&s1, cudaStreamNonBlocking);
        cudaEventCreateWithFlags(&evFork, cudaEventDisableTiming);
        cudaEventCreateWithFlags(&evCsr, cudaEventDisableTiming);
        for (int i = 0; i < 3; i++) cudaEventCreateWithFlags(&evScore[i], cudaEventDisableTiming);
        cudaEventCreateWithFlags(&evJoin, cudaEventDisableTiming);
        inited = true;
    }

    int nblk = (N + 1023) / 1024;
    int sblocks = (int)(((long long)Q * 8 + 255) / 256);

    // ---- fork: CSR build on s1, prep/score0 on s0 ----
    cudaEventRecord(evFork, 0);
    cudaStreamWaitEvent(s1, evFork, 0);

    csr_zero_kernel<<<256, 256, 0, s1>>>(N);
    csr_hist_kernel<<<1024, 256, 0, s1>>>(ei, E);
    csr_scan_local_kernel<<<nblk, 1024, 0, s1>>>(N);
    csr_scan_bsum_kernel<<<1, 256, 0, s1>>>(nblk);
    csr_scan_add_kernel<<<(N + 255) / 256, 256, 0, s1>>>(N, E);
    csr_fill_kernel<<<1024, 256, 0, s1>>>(ei, wt, E);
    cudaEventRecord(evCsr, s1);

    prep_kernel<<<(3 * 128 * 256 + 255) / 256, 256>>>(gcw, gcb, biw, bib);
    score_seg_kernel<<<sblocks, 256>>>(eli, emb, (float*)d_out, Q, 1, 0);

    cudaStreamWaitEvent(0, evCsr, 0);

    for (int i = 0; i < 3; i++) {
        // layer i+?: wait for score of the segment that g_seg still holds
        if (i >= 1) cudaStreamWaitEvent(0, evScore[i - 1], 0);
        long long gthreads = (long long)N * 32;
        int gblocks = (int)((gthreads + 255) / 256);
        gather_kernel<<<gblocks, 256>>>(emb, i == 0 ? 1 : 0, (i + 1) & 1, N);
        layer_kernel<<<(N + 127) / 128, 256, LK_SMEM>>>(i & 1, i, N, i < 2 ? 1 : 0);
        // fork score_i onto s1 (reads g_seg just written by layer i)
        cudaEventRecord(evScore[i], 0);   // marks layer i completion on s0
        cudaStreamWaitEvent(s1, evScore[i], 0);
        score_seg_kernel<<<sblocks, 256, 0, s1>>>(eli, emb, (float*)d_out, Q, 0, 1);
        cudaEventRecord(evScore[i], s1);  // re-record: now marks score i completion
    }
    cudaEventRecord(evJoin, s1);
    cudaStreamWaitEvent(0, evJoin, 0);
}

// round 14
// speedup vs baseline: 1.4708x; 1.0627x over previous
#include <cuda_runtime.h>
#include <cuda_bf16.h>
#include <cuda_fp16.h>
#include <cstdint>

#define MAXN 100000
#define MAXE 1600000
#define DIM 128

// ---------------- device scratch (no allocations allowed) ----------------
__device__ float  g_seg[(size_t)MAXN * DIM];       // current normalized segment (reused x4)
__device__ __half g_ego_h[2][(size_t)MAXN * DIM];  // ping-pong ego (fp16, unnormalized)
__device__ __nv_bfloat16 g_h_hi[(size_t)MAXN * 256];   // H=[msg|ego*msg] hi
__device__ __nv_bfloat16 g_h_lo[(size_t)MAXN * 256];   // H lo residual
__device__ __nv_bfloat16 g_wbf_hi[3 * 128 * 256];  // [layer][j][k] combined W rows, bf16 hi
__device__ __nv_bfloat16 g_wbf_lo[3 * 128 * 256];  // bf16 lo (residual)
__device__ float g_bias[3 * 128];                  // gc_b + bi_b
// CSR
__device__ int   g_deg[MAXN];
__device__ int   g_cur[MAXN];
__device__ int   g_off[MAXN + 1];
__device__ int   g_bsum[256];
__device__ int   g_ccol[MAXE];
__device__ float g_cw[MAXE];

// ================= helpers =================
__device__ __forceinline__ uint32_t smem_u32(const void* p) {
    uint32_t a;
    asm("{ .reg .u64 t; cvta.to.shared.u64 t, %1; cvt.u32.u64 %0, t; }" : "=r"(a) : "l"(p));
    return a;
}
#define LDSM_X4(r, addr) \
    asm volatile("ldmatrix.sync.aligned.m8n8.x4.shared.b16 {%0,%1,%2,%3}, [%4];" \
        : "=r"((r)[0]), "=r"((r)[1]), "=r"((r)[2]), "=r"((r)[3]) : "r"(addr))

__device__ __forceinline__ void mma16816(float* c, const uint32_t* a, const uint32_t* b) {
    asm volatile("mma.sync.aligned.m16n8k16.row.col.f32.bf16.bf16.f32 "
        "{%0,%1,%2,%3}, {%4,%5,%6,%7}, {%8,%9}, {%0,%1,%2,%3};"
        : "+f"(c[0]), "+f"(c[1]), "+f"(c[2]), "+f"(c[3])
        : "r"(a[0]), "r"(a[1]), "r"(a[2]), "r"(a[3]), "r"(b[0]), "r"(b[1]));
}
__device__ __forceinline__ void cp_async16(uint32_t smem, const void* g, uint32_t srcsize) {
    asm volatile("cp.async.cg.shared.global [%0], [%1], 16, %2;"
                 :: "r"(smem), "l"(g), "r"(srcsize) : "memory");
}
#define CP_COMMIT() asm volatile("cp.async.commit_group;" ::: "memory")
#define CP_WAIT1() asm volatile("cp.async.wait_group 1;" ::: "memory")
#define CP_WAIT0() asm volatile("cp.async.wait_group 0;" ::: "memory")

// ---------------- prep: combined W rows -> bf16 hi/lo, bias ----------------
__global__ void prep_kernel(const float* __restrict__ gcw, const float* __restrict__ gcb,
                            const float* __restrict__ biw, const float* __restrict__ bib) {
    int t = blockIdx.x * blockDim.x + threadIdx.x;
    if (t >= 3 * 128 * 256) return;
    int i = t >> 15;
    int r = t & 32767;
    int j = r >> 8, k = r & 255;
    float v;
    if (k < 128) v = gcw[i * 16384 + j * 128 + k];
    else         v = biw[i * 16384 + j * 128 + (k - 128)];
    __nv_bfloat16 hi = __float2bfloat16_rn(v);
    __nv_bfloat16 lo = __float2bfloat16_rn(v - __bfloat162float(hi));
    g_wbf_hi[t] = hi;
    g_wbf_lo[t] = lo;
    if (k == 0) g_bias[i * 128 + j] = gcb[i * 128 + j] + bib[i * 128 + j];
}

// ---------------- init: ego0 (fp16) = emb ----------------
__global__ void init_kernel(const float* __restrict__ emb, int N) {
    int t = blockIdx.x * blockDim.x + threadIdx.x;
    int total = N * 32;
    if (t >= total) return;
    float4 v = ((const float4*)emb)[t];
    __half2 h01 = __floats2half2_rn(v.x, v.y);
    __half2 h23 = __floats2half2_rn(v.z, v.w);
    uint2 w;
    w.x = *reinterpret_cast<uint32_t*>(&h01);
    w.y = *reinterpret_cast<uint32_t*>(&h23);
    ((uint2*)g_ego_h[0])[t] = w;
}

// ---------------- CSR build ----------------
__global__ void csr_zero_kernel(int N) {
    for (int i = blockIdx.x * blockDim.x + threadIdx.x; i < N; i += gridDim.x * blockDim.x) {
        g_deg[i] = 0;
        g_cur[i] = 0;
    }
}
__global__ void csr_hist_kernel(const int* __restrict__ ei, int E) {
    for (int e = blockIdx.x * blockDim.x + threadIdx.x; e < E; e += gridDim.x * blockDim.x)
        atomicAdd(&g_deg[ei[e]], 1);
}
__global__ void csr_scan_local_kernel(int N) {
    __shared__ int sm[1024];
    int b = blockIdx.x, t = threadIdx.x;
    int i = b * 1024 + t;
    int v = (i < N) ? g_deg[i] : 0;
    sm[t] = v;
    __syncthreads();
#pragma unroll
    for (int off = 1; off < 1024; off <<= 1) {
        int x = sm[t];
        int y = (t >= off) ? sm[t - off] : 0;
        __syncthreads();
        sm[t] = x + y;
        __syncthreads();
    }
    if (i < N) g_off[i] = sm[t] - v;
    if (t == 1023) g_bsum[b] = sm[t];
}
__global__ void csr_scan_bsum_kernel(int nblk) {
    __shared__ int sm[256];
    int t = threadIdx.x;
    int v = (t < nblk) ? g_bsum[t] : 0;
    sm[t] = v;
    __syncthreads();
#pragma unroll
    for (int off = 1; off < 256; off <<= 1) {
        int x = sm[t];
        int y = (t >= off) ? sm[t - off] : 0;
        __syncthreads();
        sm[t] = x + y;
        __syncthreads();
    }
    g_bsum[t] = sm[t] - v;
}
__global__ void csr_scan_add_kernel(int N, int E) {
    int i = blockIdx.x * blockDim.x + threadIdx.x;
    if (i < N) g_off[i] += g_bsum[i >> 10];
    if (i == 0) g_off[N] = E;
}
__global__ void csr_fill_kernel(const int* __restrict__ ei, const float* __restrict__ wt, int E) {
    for (int e = blockIdx.x * blockDim.x + threadIdx.x; e < E; e += gridDim.x * blockDim.x) {
        int row = ei[e];
        int pos = g_off[row] + atomicAdd(&g_cur[row], 1);
        g_ccol[pos] = ei[E + e];
        g_cw[pos] = wt[e];
    }
}

// ---------------- gather: msg = A@ego (fp16 reads), emit H=[msg|ego*msg] split-bf16 ----------------
__device__ __forceinline__ void split_pair(float x, float y, uint32_t& hi, uint32_t& lo) {
    __nv_bfloat162 h = __floats2bfloat162_rn(x, y);
    __nv_bfloat162 l = __floats2bfloat162_rn(x - __bfloat162float(h.x), y - __bfloat162float(h.y));
    hi = *reinterpret_cast<uint32_t*>(&h);
    lo = *reinterpret_cast<uint32_t*>(&l);
}
__device__ __forceinline__ float4 half8_to_f4(uint2 r) {
    __half2 a = *reinterpret_cast<__half2*>(&r.x);
    __half2 b = *reinterpret_cast<__half2*>(&r.y);
    float2 f0 = __half22float2(a);
    float2 f1 = __half22float2(b);
    return make_float4(f0.x, f0.y, f1.x, f1.y);
}

__global__ void gather_kernel(int sel, int N) {
    int g = blockIdx.x * blockDim.x + threadIdx.x;
    int n = g >> 5;
    if (n >= N) return;
    int lane = g & 31;
    int s = g_off[n], e = g_off[n + 1];
    const __half* __restrict__ ego = g_ego_h[sel];
    float4 acc = make_float4(0.f, 0.f, 0.f, 0.f);
    int i = s;
    for (; i + 4 <= e; i += 4) {
        int c0 = __ldg(g_ccol + i), c1 = __ldg(g_ccol + i + 1);
        int c2 = __ldg(g_ccol + i + 2), c3 = __ldg(g_ccol + i + 3);
        float w0 = __ldg(g_cw + i), w1 = __ldg(g_cw + i + 1);
        float w2 = __ldg(g_cw + i + 2), w3 = __ldg(g_cw + i + 3);
        uint2 r0 = __ldg((const uint2*)(ego + (size_t)c0 * DIM) + lane);
        uint2 r1 = __ldg((const uint2*)(ego + (size_t)c1 * DIM) + lane);
        uint2 r2 = __ldg((const uint2*)(ego + (size_t)c2 * DIM) + lane);
        uint2 r3 = __ldg((const uint2*)(ego + (size_t)c3 * DIM) + lane);
        float4 v0 = half8_to_f4(r0);
        float4 v1 = half8_to_f4(r1);
        float4 v2 = half8_to_f4(r2);
        float4 v3 = half8_to_f4(r3);
        acc.x += w0 * v0.x; acc.y += w0 * v0.y; acc.z += w0 * v0.z; acc.w += w0 * v0.w;
        acc.x += w1 * v1.x; acc.y += w1 * v1.y; acc.z += w1 * v1.z; acc.w += w1 * v1.w;
        acc.x += w2 * v2.x; acc.y += w2 * v2.y; acc.z += w2 * v2.z; acc.w += w2 * v2.w;
        acc.x += w3 * v3.x; acc.y += w3 * v3.y; acc.z += w3 * v3.z; acc.w += w3 * v3.w;
    }
    for (; i < e; i++) {
        int c = __ldg(g_ccol + i);
        float w = __ldg(g_cw + i);
        float4 v = half8_to_f4(__ldg((const uint2*)(ego + (size_t)c * DIM) + lane));
        acc.x += w * v.x; acc.y += w * v.y; acc.z += w * v.z; acc.w += w * v.w;
    }
    // own ego row (coalesced, fp16)
    float4 eg = half8_to_f4(__ldg((const uint2*)(ego + (size_t)n * DIM) + lane));
    float4 pr = make_float4(acc.x * eg.x, acc.y * eg.y, acc.z * eg.z, acc.w * eg.w);

    char* hi_row = (char*)(g_h_hi + (size_t)n * 256);
    char* lo_row = (char*)(g_h_lo + (size_t)n * 256);
    uint2 mh, ml, ph, pl;
    split_pair(acc.x, acc.y, mh.x, ml.x);
    split_pair(acc.z, acc.w, mh.y, ml.y);
    split_pair(pr.x, pr.y, ph.x, pl.x);
    split_pair(pr.z, pr.w, ph.y, pl.y);
    *(uint2*)(hi_row + lane * 8) = mh;
    *(uint2*)(lo_row + lane * 8) = ml;
    *(uint2*)(hi_row + 256 + lane * 8) = ph;
    *(uint2*)(lo_row + 256 + lane * 8) = pl;
}

// ================= layer GEMM: pipelined cp.async + mma.sync (bf16x3) =================
#define SMEM_B_HI 0          // 65536
#define SMEM_B_LO 65536      // 65536
#define SMEM_A    131072     // 2 stages x (Ahi 16KB + Alo 16KB)
#define LK_SMEM   196608
#define EPI_ROWPART 69632    // float [128][4]  (reuses B region post-MMA)
#define EPI_SCALE   71680    // float [128]

__device__ __forceinline__ void issue_a_stage(char* smem, int kb, int buf, int n0, int N, int tid) {
    uint32_t abase = smem_u32(smem + SMEM_A + buf * 32768);
    const char* hsrc = (const char*)g_h_hi;
    const char* lsrc = (const char*)g_h_lo;
#pragma unroll
    for (int it = 0; it < 4; it++) {
        int idx = tid + 256 * it;           // 1024 chunks
        int row = idx >> 3, c = idx & 7;
        int n = n0 + row;
        uint32_t sz = (n < N) ? 16u : 0u;
        size_t so = (size_t)(n < N ? n : 0) * 512 + kb * 128 + c * 16;
        uint32_t ci = (uint32_t)(row * 8 + (c ^ (row & 7))) * 16;
        cp_async16(abase + ci, hsrc + so, sz);
        cp_async16(abase + 16384 + ci, lsrc + so, sz);
    }
}

__global__ __launch_bounds__(256, 1) void layer_kernel(int outsel, int layer, int N, int write_ego) {
    extern __shared__ char smem[];
    const uint32_t sb = smem_u32(smem);
    const int tid = threadIdx.x;
    const int wid = tid >> 5;
    const int lid = tid & 31;
    const int n0 = blockIdx.x * 128;
    const int wm = wid >> 2;
    const int wn = wid & 3;

    // ---- resident B (full layer W, hi+lo, 128KB) + A stages ----
    {
        const char* wh = (const char*)(g_wbf_hi) + (size_t)layer * 65536;
        const char* wl = (const char*)(g_wbf_lo) + (size_t)layer * 65536;
        uint32_t bh = sb + SMEM_B_HI, bl = sb + SMEM_B_LO;
#pragma unroll
        for (int it = 0; it < 16; it++) {
            int idx = tid + 256 * it;       // 4096 chunks: [kb 4][row 128][c 8]
            int kb = idx >> 10;
            int r = (idx >> 3) & 127;
            int c = idx & 7;
            size_t so = (size_t)r * 512 + kb * 128 + c * 16;
            uint32_t ci = (uint32_t)(kb * 16384) + (uint32_t)(r * 8 + (c ^ (r & 7))) * 16;
            cp_async16(bh + ci, wh + so, 16);
            cp_async16(bl + ci, wl + so, 16);
        }
    }
    issue_a_stage(smem, 0, 0, n0, N, tid);
    CP_COMMIT();
    issue_a_stage(smem, 1, 1, n0, N, tid);
    CP_COMMIT();

    float acc[4][4][4];
#pragma unroll
    for (int mt = 0; mt < 4; mt++)
#pragma unroll
        for (int nt = 0; nt < 4; nt++)
#pragma unroll
            for (int c = 0; c < 4; c++) acc[mt][nt][c] = 0.f;

#pragma unroll
    for (int kb = 0; kb < 4; kb++) {
        if (kb < 3) CP_WAIT1(); else CP_WAIT0();
        __syncthreads();

        uint32_t abase = sb + SMEM_A + (kb & 1) * 32768;
        uint32_t bhbase = sb + SMEM_B_HI + kb * 16384;
        uint32_t blbase = sb + SMEM_B_LO + kb * 16384;
#pragma unroll
        for (int ks = 0; ks < 4; ks++) {
            uint32_t ahi[4][4], alo[4][4];
            int lr = lid & 15, lk = lid >> 4;
#pragma unroll
            for (int mt = 0; mt < 4; mt++) {
                int r = wm * 64 + mt * 16 + lr;
                int kc = ks * 2 + lk;
                uint32_t off = (uint32_t)(r * 8 + (kc ^ (r & 7))) * 16;
                LDSM_X4(ahi[mt], abase + off);
                LDSM_X4(alo[mt], abase + 16384 + off);
            }
            uint32_t bhi[2][4], blo[2][4];
            int nr = (lid & 7) + ((lid >> 4) << 3);
            int nk = (lid >> 3) & 1;
#pragma unroll
            for (int np = 0; np < 2; np++) {
                int r = wn * 32 + np * 16 + nr;
                int kc = ks * 2 + nk;
                uint32_t off = (uint32_t)(r * 8 + (kc ^ (r & 7))) * 16;
                LDSM_X4(bhi[np], bhbase + off);
                LDSM_X4(blo[np], blbase + off);
            }
#pragma unroll
            for (int mt = 0; mt < 4; mt++)
#pragma unroll
                for (int nt = 0; nt < 4; nt++) {
                    const uint32_t* bh = &bhi[nt >> 1][(nt & 1) * 2];
                    const uint32_t* bl = &blo[nt >> 1][(nt & 1) * 2];
                    mma16816(acc[mt][nt], ahi[mt], bh);
                    mma16816(acc[mt][nt], ahi[mt], bl);
                    mma16816(acc[mt][nt], alo[mt], bh);
                }
        }
        __syncthreads();
        if (kb + 2 < 4) { issue_a_stage(smem, kb + 2, kb & 1, n0, N, tid); CP_COMMIT(); }
    }

    // ================= epilogue (reuses B SMEM region) =================
    float* stage = (float*)smem;                      // [128][136]
    float* rowpart = (float*)(smem + EPI_ROWPART);    // [128][4]
    const float* bias = g_bias + layer * 128;
    int qid = lid >> 2, qt = lid & 3;
#pragma unroll
    for (int mt = 0; mt < 4; mt++) {
        int rA = wm * 64 + mt * 16 + qid;
        int rB = rA + 8;
        float sqa = 0.f, sqb = 0.f;
#pragma unroll
        for (int nt = 0; nt < 4; nt++) {
            int col = wn * 32 + nt * 8 + 2 * qt;
            float b0 = __ldg(bias + col), b1 = __ldg(bias + col + 1);
            float* c = acc[mt][nt];
            float x0 = c[0] + b0, x1 = c[1] + b1;
            float y0 = c[2] + b0, y1 = c[3] + b1;
            x0 = x0 > 0.f ? x0 : 0.2f * x0;
            x1 = x1 > 0.f ? x1 : 0.2f * x1;
            y0 = y0 > 0.f ? y0 : 0.2f * y0;
            y1 = y1 > 0.f ? y1 : 0.2f * y1;
            stage[rA * 136 + col] = x0;
            stage[rA * 136 + col + 1] = x1;
            stage[rB * 136 + col] = y0;
            stage[rB * 136 + col + 1] = y1;
            sqa += x0 * x0 + x1 * x1;
            sqb += y0 * y0 + y1 * y1;
        }
        sqa += __shfl_xor_sync(0xffffffffu, sqa, 1);
        sqa += __shfl_xor_sync(0xffffffffu, sqa, 2);
        sqb += __shfl_xor_sync(0xffffffffu, sqb, 1);
        sqb += __shfl_xor_sync(0xffffffffu, sqb, 2);
        if (qt == 0) {
            rowpart[rA * 4 + wn] = sqa;
            rowpart[rB * 4 + wn] = sqb;
        }
    }
    __syncthreads();
    float* scl = (float*)(smem + EPI_SCALE);
    if (tid < 128) {
        float tot = rowpart[tid * 4] + rowpart[tid * 4 + 1] + rowpart[tid * 4 + 2] + rowpart[tid * 4 + 3];
        scl[tid] = 1.0f / fmaxf(sqrtf(tot), 1e-12f);
    }
    __syncthreads();
    __half* ego_out = g_ego_h[outsel];
#pragma unroll
    for (int it = 0; it < 16; it++) {
        int idx = tid + 256 * it;
        int r = idx >> 5, j = idx & 31;
        int n = n0 + r;
        if (n < N) {
            float4 v = *(const float4*)(stage + r * 136 + j * 4);
            if (write_ego) {
                __half2 h01 = __floats2half2_rn(v.x, v.y);
                __half2 h23 = __floats2half2_rn(v.z, v.w);
                uint2 w;
                w.x = *reinterpret_cast<uint32_t*>(&h01);
                w.y = *reinterpret_cast<uint32_t*>(&h23);
                ((uint2*)(ego_out + (size_t)n * DIM))[j] = w;
            }
            float s = scl[r];
            float4 sv = make_float4(v.x * s, v.y * s, v.z * s, v.w * s);
            ((float4*)(g_seg + (size_t)n * DIM))[j] = sv;
        }
    }
}

// ---------------- segment scoring: out[q] (+)= dot(row[s], row[d]) over 128 ----------------
__global__ void score_seg_kernel(const int* __restrict__ eli, const float* __restrict__ emb,
                                 float* __restrict__ out, int Q, int use_emb, int add) {
    int g = blockIdx.x * blockDim.x + threadIdx.x;
    int q = g >> 3;
    if (q >= Q) return;
    int lane = g & 7;
    int s = __ldg(eli + q);
    int d = __ldg(eli + Q + q);
    const float* base = use_emb ? emb : (const float*)g_seg;
    const float4* ps = (const float4*)(base + (size_t)s * DIM);
    const float4* pd = (const float4*)(base + (size_t)d * DIM);
    float sum = 0.f;
#pragma unroll
    for (int t = 0; t < 4; t++) {
        float4 a = __ldg(ps + lane + 8 * t);
        float4 b = __ldg(pd + lane + 8 * t);
        sum += a.x * b.x + a.y * b.y + a.z * b.z + a.w * b.w;
    }
    sum += __shfl_xor_sync(0xffffffffu, sum, 1);
    sum += __shfl_xor_sync(0xffffffffu, sum, 2);
    sum += __shfl_xor_sync(0xffffffffu, sum, 4);
    if (lane == 0) {
        if (add) out[q] += sum;
        else     out[q] = sum;
    }
}

// ---------------- launch ----------------
extern "C" void kernel_launch(void* const* d_in, const int* in_sizes, int n_in,
                              void* d_out, int out_size) {
    const int*   ei  = (const int*)d_in[0];
    const int*   eli = (const int*)d_in[1];
    const float* wt  = (const float*)d_in[2];
    const float* emb = (const float*)d_in[3];
    const float* gcw = (const float*)d_in[4];
    const float* gcb = (const float*)d_in[5];
    const float* biw = (const float*)d_in[6];
    const float* bib = (const float*)d_in[7];

    int E = in_sizes[2];
    int Q = in_sizes[1] / 2;
    int N = in_sizes[3] / DIM;

    static bool inited = false;
    static cudaStream_t s1;
    static cudaEvent_t evFork, evCsr, evScore[3], evJoin;
    if (!inited) {
        cudaFuncSetAttribute(layer_kernel, cudaFuncAttributeMaxDynamicSharedMemorySize, LK_SMEM);
        cudaStreamCreateWithFlags(&s1, cudaStreamNonBlocking);
        cudaEventCreateWithFlags(&evFork, cudaEventDisableTiming);
        cudaEventCreateWithFlags(&evCsr, cudaEventDisableTiming);
        for (int i = 0; i < 3; i++) cudaEventCreateWithFlags(&evScore[i], cudaEventDisableTiming);
        cudaEventCreateWithFlags(&evJoin, cudaEventDisableTiming);
        inited = true;
    }

    int nblk = (N + 1023) / 1024;
    int sblocks = (int)(((long long)Q * 8 + 255) / 256);

    // ---- fork: CSR build on s1, prep/init/score0 on s0 ----
    cudaEventRecord(evFork, 0);
    cudaStreamWaitEvent(s1, evFork, 0);

    csr_zero_kernel<<<256, 256, 0, s1>>>(N);
    csr_hist_kernel<<<1024, 256, 0, s1>>>(ei, E);
    csr_scan_local_kernel<<<nblk, 1024, 0, s1>>>(N);
    csr_scan_bsum_kernel<<<1, 256, 0, s1>>>(nblk);
    csr_scan_add_kernel<<<(N + 255) / 256, 256, 0, s1>>>(N, E);
    csr_fill_kernel<<<1024, 256, 0, s1>>>(ei, wt, E);
    cudaEventRecord(evCsr, s1);

    prep_kernel<<<(3 * 128 * 256 + 255) / 256, 256>>>(gcw, gcb, biw, bib);
    init_kernel<<<(N * 32 + 255) / 256, 256>>>(emb, N);
    score_seg_kernel<<<sblocks, 256>>>(eli, emb, (float*)d_out, Q, 1, 0);

    cudaStreamWaitEvent(0, evCsr, 0);

    for (int i = 0; i < 3; i++) {
        if (i >= 1) cudaStreamWaitEvent(0, evScore[i - 1], 0);
        long long gthreads = (long long)N * 32;
        int gblocks = (int)((gthreads + 255) / 256);
        gather_kernel<<<gblocks, 256>>>(i & 1 ? 1 : 0, N);
        layer_kernel<<<(N + 127) / 128, 256, LK_SMEM>>>((i + 1) & 1, i, N, i < 2 ? 1 : 0);
        cudaEventRecord(evScore[i], 0);   // marks layer i completion on s0
        cudaStreamWaitEvent(s1, evScore[i], 0);
        score_seg_kernel<<<sblocks, 256, 0, s1>>>(eli, emb, (float*)d_out, Q, 0, 1);
        cudaEventRecord(evScore[i], s1);  // re-record: now marks score i completion
    }
    cudaEventRecord(evJoin, s1);
    cudaStreamWaitEvent(0, evJoin, 0);
}

// round 15
// speedup vs baseline: 2.0707x; 1.4079x over previous
#include <cuda_runtime.h>
#include <cuda_bf16.h>
#include <cuda_fp16.h>
#include <cstdint>

#define MAXN 100000
#define MAXE 1600000
#define DIM 128

// ---------------- device scratch (no allocations allowed) ----------------
__device__ float  g_seg[(size_t)MAXN * DIM];       // current normalized segment (reused x4)
__device__ __half g_ego_h[2][(size_t)MAXN * DIM];  // ping-pong ego (fp16, unnormalized)
__device__ __half g_h[(size_t)MAXN * 256];         // H=[msg|ego*msg] fp16
__device__ __half g_wh[3 * 128 * 256];             // [layer][j][k] combined W rows, fp16
__device__ float g_bias[3 * 128];                  // gc_b + bi_b
// CSR
__device__ int   g_deg[MAXN];
__device__ int   g_cur[MAXN];
__device__ int   g_off[MAXN + 1];
__device__ int   g_bsum[256];
__device__ int   g_ccol[MAXE];
__device__ float g_cw[MAXE];

// ================= helpers =================
__device__ __forceinline__ uint32_t smem_u32(const void* p) {
    uint32_t a;
    asm("{ .reg .u64 t; cvta.to.shared.u64 t, %1; cvt.u32.u64 %0, t; }" : "=r"(a) : "l"(p));
    return a;
}
#define LDSM_X4(r, addr) \
    asm volatile("ldmatrix.sync.aligned.m8n8.x4.shared.b16 {%0,%1,%2,%3}, [%4];" \
        : "=r"((r)[0]), "=r"((r)[1]), "=r"((r)[2]), "=r"((r)[3]) : "r"(addr))

__device__ __forceinline__ void mma16816_f16(float* c, const uint32_t* a, const uint32_t* b) {
    asm volatile("mma.sync.aligned.m16n8k16.row.col.f32.f16.f16.f32 "
        "{%0,%1,%2,%3}, {%4,%5,%6,%7}, {%8,%9}, {%0,%1,%2,%3};"
        : "+f"(c[0]), "+f"(c[1]), "+f"(c[2]), "+f"(c[3])
        : "r"(a[0]), "r"(a[1]), "r"(a[2]), "r"(a[3]), "r"(b[0]), "r"(b[1]));
}
__device__ __forceinline__ void cp_async16(uint32_t smem, const void* g, uint32_t srcsize) {
    asm volatile("cp.async.cg.shared.global [%0], [%1], 16, %2;"
                 :: "r"(smem), "l"(g), "r"(srcsize) : "memory");
}
#define CP_COMMIT() asm volatile("cp.async.commit_group;" ::: "memory")
#define CP_WAIT1() asm volatile("cp.async.wait_group 1;" ::: "memory")
#define CP_WAIT0() asm volatile("cp.async.wait_group 0;" ::: "memory")

// ---------------- prep: combined W rows -> fp16, bias ----------------
__global__ void prep_kernel(const float* __restrict__ gcw, const float* __restrict__ gcb,
                            const float* __restrict__ biw, const float* __restrict__ bib) {
    int t = blockIdx.x * blockDim.x + threadIdx.x;
    if (t >= 3 * 128 * 256) return;
    int i = t >> 15;
    int r = t & 32767;
    int j = r >> 8, k = r & 255;
    float v;
    if (k < 128) v = gcw[i * 16384 + j * 128 + k];
    else         v = biw[i * 16384 + j * 128 + (k - 128)];
    g_wh[t] = __float2half_rn(v);
    if (k == 0) g_bias[i * 128 + j] = gcb[i * 128 + j] + bib[i * 128 + j];
}

// ---------------- init: ego0 (fp16) = emb ----------------
__global__ void init_kernel(const float* __restrict__ emb, int N) {
    int t = blockIdx.x * blockDim.x + threadIdx.x;
    int total = N * 32;
    if (t >= total) return;
    float4 v = ((const float4*)emb)[t];
    __half2 h01 = __floats2half2_rn(v.x, v.y);
    __half2 h23 = __floats2half2_rn(v.z, v.w);
    uint2 w;
    w.x = *reinterpret_cast<uint32_t*>(&h01);
    w.y = *reinterpret_cast<uint32_t*>(&h23);
    ((uint2*)g_ego_h[0])[t] = w;
}

// ---------------- CSR build ----------------
__global__ void csr_zero_kernel(int N) {
    for (int i = blockIdx.x * blockDim.x + threadIdx.x; i < N; i += gridDim.x * blockDim.x) {
        g_deg[i] = 0;
        g_cur[i] = 0;
    }
}
__global__ void csr_hist_kernel(const int* __restrict__ ei, int E) {
    for (int e = blockIdx.x * blockDim.x + threadIdx.x; e < E; e += gridDim.x * blockDim.x)
        atomicAdd(&g_deg[ei[e]], 1);
}
__global__ void csr_scan_local_kernel(int N) {
    __shared__ int sm[1024];
    int b = blockIdx.x, t = threadIdx.x;
    int i = b * 1024 + t;
    int v = (i < N) ? g_deg[i] : 0;
    sm[t] = v;
    __syncthreads();
#pragma unroll
    for (int off = 1; off < 1024; off <<= 1) {
        int x = sm[t];
        int y = (t >= off) ? sm[t - off] : 0;
        __syncthreads();
        sm[t] = x + y;
        __syncthreads();
    }
    if (i < N) g_off[i] = sm[t] - v;
    if (t == 1023) g_bsum[b] = sm[t];
}
__global__ void csr_scan_bsum_kernel(int nblk) {
    __shared__ int sm[256];
    int t = threadIdx.x;
    int v = (t < nblk) ? g_bsum[t] : 0;
    sm[t] = v;
    __syncthreads();
#pragma unroll
    for (int off = 1; off < 256; off <<= 1) {
        int x = sm[t];
        int y = (t >= off) ? sm[t - off] : 0;
        __syncthreads();
        sm[t] = x + y;
        __syncthreads();
    }
    g_bsum[t] = sm[t] - v;
}
__global__ void csr_scan_add_kernel(int N, int E) {
    int i = blockIdx.x * blockDim.x + threadIdx.x;
    if (i < N) g_off[i] += g_bsum[i >> 10];
    if (i == 0) g_off[N] = E;
}
__global__ void csr_fill_kernel(const int* __restrict__ ei, const float* __restrict__ wt, int E) {
    for (int e = blockIdx.x * blockDim.x + threadIdx.x; e < E; e += gridDim.x * blockDim.x) {
        int row = ei[e];
        int pos = g_off[row] + atomicAdd(&g_cur[row], 1);
        g_ccol[pos] = ei[E + e];
        g_cw[pos] = wt[e];
    }
}

// ---------------- gather: msg = A@ego (fp16 reads), emit H=[msg|ego*msg] fp16 ----------------
__device__ __forceinline__ float4 half8_to_f4(uint2 r) {
    __half2 a = *reinterpret_cast<__half2*>(&r.x);
    __half2 b = *reinterpret_cast<__half2*>(&r.y);
    float2 f0 = __half22float2(a);
    float2 f1 = __half22float2(b);
    return make_float4(f0.x, f0.y, f1.x, f1.y);
}
__device__ __forceinline__ uint2 f4_to_half8(float4 v) {
    __half2 h01 = __floats2half2_rn(v.x, v.y);
    __half2 h23 = __floats2half2_rn(v.z, v.w);
    uint2 w;
    w.x = *reinterpret_cast<uint32_t*>(&h01);
    w.y = *reinterpret_cast<uint32_t*>(&h23);
    return w;
}

__global__ void gather_kernel(int sel, int N) {
    int g = blockIdx.x * blockDim.x + threadIdx.x;
    int n = g >> 5;
    if (n >= N) return;
    int lane = g & 31;
    int s = g_off[n], e = g_off[n + 1];
    const __half* __restrict__ ego = g_ego_h[sel];
    float4 acc = make_float4(0.f, 0.f, 0.f, 0.f);
    int i = s;
    for (; i + 4 <= e; i += 4) {
        int c0 = __ldg(g_ccol + i), c1 = __ldg(g_ccol + i + 1);
        int c2 = __ldg(g_ccol + i + 2), c3 = __ldg(g_ccol + i + 3);
        float w0 = __ldg(g_cw + i), w1 = __ldg(g_cw + i + 1);
        float w2 = __ldg(g_cw + i + 2), w3 = __ldg(g_cw + i + 3);
        uint2 r0 = __ldg((const uint2*)(ego + (size_t)c0 * DIM) + lane);
        uint2 r1 = __ldg((const uint2*)(ego + (size_t)c1 * DIM) + lane);
        uint2 r2 = __ldg((const uint2*)(ego + (size_t)c2 * DIM) + lane);
        uint2 r3 = __ldg((const uint2*)(ego + (size_t)c3 * DIM) + lane);
        float4 v0 = half8_to_f4(r0);
        float4 v1 = half8_to_f4(r1);
        float4 v2 = half8_to_f4(r2);
        float4 v3 = half8_to_f4(r3);
        acc.x += w0 * v0.x; acc.y += w0 * v0.y; acc.z += w0 * v0.z; acc.w += w0 * v0.w;
        acc.x += w1 * v1.x; acc.y += w1 * v1.y; acc.z += w1 * v1.z; acc.w += w1 * v1.w;
        acc.x += w2 * v2.x; acc.y += w2 * v2.y; acc.z += w2 * v2.z; acc.w += w2 * v2.w;
        acc.x += w3 * v3.x; acc.y += w3 * v3.y; acc.z += w3 * v3.z; acc.w += w3 * v3.w;
    }
    for (; i < e; i++) {
        int c = __ldg(g_ccol + i);
        float w = __ldg(g_cw + i);
        float4 v = half8_to_f4(__ldg((const uint2*)(ego + (size_t)c * DIM) + lane));
        acc.x += w * v.x; acc.y += w * v.y; acc.z += w * v.z; acc.w += w * v.w;
    }
    float4 eg = half8_to_f4(__ldg((const uint2*)(ego + (size_t)n * DIM) + lane));
    float4 pr = make_float4(acc.x * eg.x, acc.y * eg.y, acc.z * eg.z, acc.w * eg.w);

    char* h_row = (char*)(g_h + (size_t)n * 256);
    *(uint2*)(h_row + lane * 8) = f4_to_half8(acc);
    *(uint2*)(h_row + 256 + lane * 8) = f4_to_half8(pr);
}

// ================= layer GEMM: pipelined cp.async + mma.sync fp16 (single pass) =================
// Block 128x128, K=256 in 4 stages of 64. 256 threads, 8 warps, warp tile 64x32. 2 CTAs/SM.
#define SMEM_B    0          // 65536 (4 kb tiles x 16KB, resident)
#define SMEM_A    65536      // 2 stages x 16KB
#define LK_SMEM   98304
#define EPI_ROWPART 69632    // float [128][4]
#define EPI_SCALE   71680    // float [128]

__device__ __forceinline__ void issue_a_stage(char* smem, int kb, int buf, int n0, int N, int tid) {
    uint32_t abase = smem_u32(smem + SMEM_A + buf * 16384);
    const char* hsrc = (const char*)g_h;
#pragma unroll
    for (int it = 0; it < 4; it++) {
        int idx = tid + 256 * it;           // 1024 chunks: [row 128][c 8]
        int row = idx >> 3, c = idx & 7;
        int n = n0 + row;
        uint32_t sz = (n < N) ? 16u : 0u;
        size_t so = (size_t)(n < N ? n : 0) * 512 + kb * 128 + c * 16;
        uint32_t ci = (uint32_t)(row * 8 + (c ^ (row & 7))) * 16;
        cp_async16(abase + ci, hsrc + so, sz);
    }
}

__global__ __launch_bounds__(256, 2) void layer_kernel(int outsel, int layer, int N, int write_ego) {
    extern __shared__ char smem[];
    const uint32_t sb = smem_u32(smem);
    const int tid = threadIdx.x;
    const int wid = tid >> 5;
    const int lid = tid & 31;
    const int n0 = blockIdx.x * 128;
    const int wm = wid >> 2;
    const int wn = wid & 3;

    // ---- resident B (full layer W fp16, 64KB) + A stages ----
    {
        const char* wsrc = (const char*)(g_wh) + (size_t)layer * 65536;
        uint32_t bb = sb + SMEM_B;
#pragma unroll
        for (int it = 0; it < 16; it++) {
            int idx = tid + 256 * it;       // 4096 chunks: [kb 4][row 128][c 8]
            int kb = idx >> 10;
            int r = (idx >> 3) & 127;
            int c = idx & 7;
            size_t so = (size_t)r * 512 + kb * 128 + c * 16;
            uint32_t ci = (uint32_t)(kb * 16384) + (uint32_t)(r * 8 + (c ^ (r & 7))) * 16;
            cp_async16(bb + ci, wsrc + so, 16);
        }
    }
    issue_a_stage(smem, 0, 0, n0, N, tid);
    CP_COMMIT();
    issue_a_stage(smem, 1, 1, n0, N, tid);
    CP_COMMIT();

    float acc[4][4][4];
#pragma unroll
    for (int mt = 0; mt < 4; mt++)
#pragma unroll
        for (int nt = 0; nt < 4; nt++)
#pragma unroll
            for (int c = 0; c < 4; c++) acc[mt][nt][c] = 0.f;

#pragma unroll
    for (int kb = 0; kb < 4; kb++) {
        if (kb < 3) CP_WAIT1(); else CP_WAIT0();
        __syncthreads();

        uint32_t abase = sb + SMEM_A + (kb & 1) * 16384;
        uint32_t bbase = sb + SMEM_B + kb * 16384;
#pragma unroll
        for (int ks = 0; ks < 4; ks++) {
            uint32_t a[4][4];
            int lr = lid & 15, lk = lid >> 4;
#pragma unroll
            for (int mt = 0; mt < 4; mt++) {
                int r = wm * 64 + mt * 16 + lr;
                int kc = ks * 2 + lk;
                uint32_t off = (uint32_t)(r * 8 + (kc ^ (r & 7))) * 16;
                LDSM_X4(a[mt], abase + off);
            }
            uint32_t b[2][4];
            int nr = (lid & 7) + ((lid >> 4) << 3);
            int nk = (lid >> 3) & 1;
#pragma unroll
            for (int np = 0; np < 2; np++) {
                int r = wn * 32 + np * 16 + nr;
                int kc = ks * 2 + nk;
                uint32_t off = (uint32_t)(r * 8 + (kc ^ (r & 7))) * 16;
                LDSM_X4(b[np], bbase + off);
            }
#pragma unroll
            for (int mt = 0; mt < 4; mt++)
#pragma unroll
                for (int nt = 0; nt < 4; nt++)
                    mma16816_f16(acc[mt][nt], a[mt], &b[nt >> 1][(nt & 1) * 2]);
        }
        __syncthreads();
        if (kb + 2 < 4) { issue_a_stage(smem, kb + 2, kb & 1, n0, N, tid); CP_COMMIT(); }
    }

    // ================= epilogue (reuses SMEM) =================
    float* stage = (float*)smem;                      // [128][136]
    float* rowpart = (float*)(smem + EPI_ROWPART);    // [128][4]
    const float* bias = g_bias + layer * 128;
    int qid = lid >> 2, qt = lid & 3;
#pragma unroll
    for (int mt = 0; mt < 4; mt++) {
        int rA = wm * 64 + mt * 16 + qid;
        int rB = rA + 8;
        float sqa = 0.f, sqb = 0.f;
#pragma unroll
        for (int nt = 0; nt < 4; nt++) {
            int col = wn * 32 + nt * 8 + 2 * qt;
            float b0 = __ldg(bias + col), b1 = __ldg(bias + col + 1);
            float* c = acc[mt][nt];
            float x0 = c[0] + b0, x1 = c[1] + b1;
            float y0 = c[2] + b0, y1 = c[3] + b1;
            x0 = x0 > 0.f ? x0 : 0.2f * x0;
            x1 = x1 > 0.f ? x1 : 0.2f * x1;
            y0 = y0 > 0.f ? y0 : 0.2f * y0;
            y1 = y1 > 0.f ? y1 : 0.2f * y1;
            stage[rA * 136 + col] = x0;
            stage[rA * 136 + col + 1] = x1;
            stage[rB * 136 + col] = y0;
            stage[rB * 136 + col + 1] = y1;
            sqa += x0 * x0 + x1 * x1;
            sqb += y0 * y0 + y1 * y1;
        }
        sqa += __shfl_xor_sync(0xffffffffu, sqa, 1);
        sqa += __shfl_xor_sync(0xffffffffu, sqa, 2);
        sqb += __shfl_xor_sync(0xffffffffu, sqb, 1);
        sqb += __shfl_xor_sync(0xffffffffu, sqb, 2);
        if (qt == 0) {
            rowpart[rA * 4 + wn] = sqa;
            rowpart[rB * 4 + wn] = sqb;
        }
    }
    __syncthreads();
    float* scl = (float*)(smem + EPI_SCALE);
    if (tid < 128) {
        float tot = rowpart[tid * 4] + rowpart[tid * 4 + 1] + rowpart[tid * 4 + 2] + rowpart[tid * 4 + 3];
        scl[tid] = 1.0f / fmaxf(sqrtf(tot), 1e-12f);
    }
    __syncthreads();
    __half* ego_out = g_ego_h[outsel];
#pragma unroll
    for (int it = 0; it < 16; it++) {
        int idx = tid + 256 * it;
        int r = idx >> 5, j = idx & 31;
        int n = n0 + r;
        if (n < N) {
            float4 v = *(const float4*)(stage + r * 136 + j * 4);
            if (write_ego)
                ((uint2*)(ego_out + (size_t)n * DIM))[j] = f4_to_half8(v);
            float s = scl[r];
            float4 sv = make_float4(v.x * s, v.y * s, v.z * s, v.w * s);
            ((float4*)(g_seg + (size_t)n * DIM))[j] = sv;
        }
    }
}

// ---------------- segment scoring: out[q] (+)= dot(row[s], row[d]) over 128 ----------------
__global__ void score_seg_kernel(const int* __restrict__ eli, const float* __restrict__ emb,
                                 float* __restrict__ out, int Q, int use_emb, int add) {
    int g = blockIdx.x * blockDim.x + threadIdx.x;
    int q = g >> 3;
    if (q >= Q) return;
    int lane = g & 7;
    int s = __ldg(eli + q);
    int d = __ldg(eli + Q + q);
    const float* base = use_emb ? emb : (const float*)g_seg;
    const float4* ps = (const float4*)(base + (size_t)s * DIM);
    const float4* pd = (const float4*)(base + (size_t)d * DIM);
    float sum = 0.f;
#pragma unroll
    for (int t = 0; t < 4; t++) {
        float4 a = __ldg(ps + lane + 8 * t);
        float4 b = __ldg(pd + lane + 8 * t);
        sum += a.x * b.x + a.y * b.y + a.z * b.z + a.w * b.w;
    }
    sum += __shfl_xor_sync(0xffffffffu, sum, 1);
    sum += __shfl_xor_sync(0xffffffffu, sum, 2);
    sum += __shfl_xor_sync(0xffffffffu, sum, 4);
    if (lane == 0) {
        if (add) out[q] += sum;
        else     out[q] = sum;
    }
}

// ---------------- launch ----------------
extern "C" void kernel_launch(void* const* d_in, const int* in_sizes, int n_in,
                              void* d_out, int out_size) {
    const int*   ei  = (const int*)d_in[0];
    const int*   eli = (const int*)d_in[1];
    const float* wt  = (const float*)d_in[2];
    const float* emb = (const float*)d_in[3];
    const float* gcw = (const float*)d_in[4];
    const float* gcb = (const float*)d_in[5];
    const float* biw = (const float*)d_in[6];
    const float* bib = (const float*)d_in[7];

    int E = in_sizes[2];
    int Q = in_sizes[1] / 2;
    int N = in_sizes[3] / DIM;

    static bool inited = false;
    static cudaStream_t s1;
    static cudaEvent_t evFork, evCsr, evScore[3], evJoin;
    if (!inited) {
        cudaFuncSetAttribute(layer_kernel, cudaFuncAttributeMaxDynamicSharedMemorySize, LK_SMEM);
        cudaStreamCreateWithFlags(&s1, cudaStreamNonBlocking);
        cudaEventCreateWithFlags(&evFork, cudaEventDisableTiming);
        cudaEventCreateWithFlags(&evCsr, cudaEventDisableTiming);
        for (int i = 0; i < 3; i++) cudaEventCreateWithFlags(&evScore[i], cudaEventDisableTiming);
        cudaEventCreateWithFlags(&evJoin, cudaEventDisableTiming);
        inited = true;
    }

    int nblk = (N + 1023) / 1024;
    int sblocks = (int)(((long long)Q * 8 + 255) / 256);

    // ---- fork: CSR build on s1, prep/init/score0 on s0 ----
    cudaEventRecord(evFork, 0);
    cudaStreamWaitEvent(s1, evFork, 0);

    csr_zero_kernel<<<256, 256, 0, s1>>>(N);
    csr_hist_kernel<<<1024, 256, 0, s1>>>(ei, E);
    csr_scan_local_kernel<<<nblk, 1024, 0, s1>>>(N);
    csr_scan_bsum_kernel<<<1, 256, 0, s1>>>(nblk);
    csr_scan_add_kernel<<<(N + 255) / 256, 256, 0, s1>>>(N, E);
    csr_fill_kernel<<<1024, 256, 0, s1>>>(ei, wt, E);
    cudaEventRecord(evCsr, s1);

    prep_kernel<<<(3 * 128 * 256 + 255) / 256, 256>>>(gcw, gcb, biw, bib);
    init_kernel<<<(N * 32 + 255) / 256, 256>>>(emb, N);
    score_seg_kernel<<<sblocks, 256>>>(eli, emb, (float*)d_out, Q, 1, 0);

    cudaStreamWaitEvent(0, evCsr, 0);

    for (int i = 0; i < 3; i++) {
        if (i >= 1) cudaStreamWaitEvent(0, evScore[i - 1], 0);
        long long gthreads = (long long)N * 32;
        int gblocks = (int)((gthreads + 255) / 256);
        gather_kernel<<<gblocks, 256>>>(i & 1 ? 1 : 0, N);
        layer_kernel<<<(N + 127) / 128, 256, LK_SMEM>>>((i + 1) & 1, i, N, i < 2 ? 1 : 0);
        cudaEventRecord(evScore[i], 0);   // marks layer i completion on s0
        cudaStreamWaitEvent(s1, evScore[i], 0);
        score_seg_kernel<<<sblocks, 256, 0, s1>>>(eli, emb, (float*)d_out, Q, 0, 1);
        cudaEventRecord(evScore[i], s1);  // re-record: now marks score i completion
    }
    cudaEventRecord(evJoin, s1);
    cudaStreamWaitEvent(0, evJoin, 0);
}

// round 17
// speedup vs baseline: 2.1718x; 1.0488x over previous
#include <cuda_runtime.h>
#include <cuda_bf16.h>
#include <cuda_fp16.h>
#include <cstdint>

#define MAXN 100000
#define MAXE 1600000
#define DIM 128

// ---------------- device scratch (no allocations allowed) ----------------
__device__ __half g_seg[(size_t)MAXN * DIM];       // current normalized segment (fp16, reused x4)
__device__ __half g_ego_h[2][(size_t)MAXN * DIM];  // ping-pong ego (fp16, unnormalized)
__device__ __half g_h[(size_t)MAXN * 256];         // H=[msg|ego*msg] fp16
__device__ __half g_wh[3 * 128 * 256];             // [layer][j][k] combined W rows, fp16
__device__ float g_bias[3 * 128];                  // gc_b + bi_b
// CSR
__device__ int   g_deg[MAXN];
__device__ int   g_cur[MAXN];
__device__ int   g_off[MAXN + 1];
__device__ int   g_bsum[256];
__device__ int   g_ccol[MAXE];
__device__ float g_cw[MAXE];

// ================= helpers =================
__device__ __forceinline__ uint32_t smem_u32(const void* p) {
    uint32_t a;
    asm("{ .reg .u64 t; cvta.to.shared.u64 t, %1; cvt.u32.u64 %0, t; }" : "=r"(a) : "l"(p));
    return a;
}
#define LDSM_X4(r, addr) \
    asm volatile("ldmatrix.sync.aligned.m8n8.x4.shared.b16 {%0,%1,%2,%3}, [%4];" \
        : "=r"((r)[0]), "=r"((r)[1]), "=r"((r)[2]), "=r"((r)[3]) : "r"(addr))

__device__ __forceinline__ void mma16816_f16(float* c, const uint32_t* a, const uint32_t* b) {
    asm volatile("mma.sync.aligned.m16n8k16.row.col.f32.f16.f16.f32 "
        "{%0,%1,%2,%3}, {%4,%5,%6,%7}, {%8,%9}, {%0,%1,%2,%3};"
        : "+f"(c[0]), "+f"(c[1]), "+f"(c[2]), "+f"(c[3])
        : "r"(a[0]), "r"(a[1]), "r"(a[2]), "r"(a[3]), "r"(b[0]), "r"(b[1]));
}
__device__ __forceinline__ void cp_async16(uint32_t smem, const void* g, uint32_t srcsize) {
    asm volatile("cp.async.cg.shared.global [%0], [%1], 16, %2;"
                 :: "r"(smem), "l"(g), "r"(srcsize) : "memory");
}
#define CP_COMMIT() asm volatile("cp.async.commit_group;" ::: "memory")
#define CP_WAIT1() asm volatile("cp.async.wait_group 1;" ::: "memory")
#define CP_WAIT0() asm volatile("cp.async.wait_group 0;" ::: "memory")

// NOTE: uint2 = 8 bytes = 4 halves.
__device__ __forceinline__ float4 half4_to_f4(uint2 r) {
    __half2 a = *reinterpret_cast<__half2*>(&r.x);
    __half2 b = *reinterpret_cast<__half2*>(&r.y);
    float2 f0 = __half22float2(a);
    float2 f1 = __half22float2(b);
    return make_float4(f0.x, f0.y, f1.x, f1.y);
}
__device__ __forceinline__ uint2 f4_to_half4(float4 v) {
    __half2 h01 = __floats2half2_rn(v.x, v.y);
    __half2 h23 = __floats2half2_rn(v.z, v.w);
    uint2 w;
    w.x = *reinterpret_cast<uint32_t*>(&h01);
    w.y = *reinterpret_cast<uint32_t*>(&h23);
    return w;
}

// ---------------- prep: combined W rows -> fp16, bias ----------------
__global__ void prep_kernel(const float* __restrict__ gcw, const float* __restrict__ gcb,
                            const float* __restrict__ biw, const float* __restrict__ bib) {
    int t = blockIdx.x * blockDim.x + threadIdx.x;
    if (t >= 3 * 128 * 256) return;
    int i = t >> 15;
    int r = t & 32767;
    int j = r >> 8, k = r & 255;
    float v;
    if (k < 128) v = gcw[i * 16384 + j * 128 + k];
    else         v = biw[i * 16384 + j * 128 + (k - 128)];
    g_wh[t] = __float2half_rn(v);
    if (k == 0) g_bias[i * 128 + j] = gcb[i * 128 + j] + bib[i * 128 + j];
}

// ---------------- init: ego0 (fp16) = emb ----------------
__global__ void init_kernel(const float* __restrict__ emb, int N) {
    int t = blockIdx.x * blockDim.x + threadIdx.x;
    int total = N * 32;
    if (t >= total) return;
    float4 v = ((const float4*)emb)[t];
    ((uint2*)g_ego_h[0])[t] = f4_to_half4(v);
}

// ---------------- CSR build ----------------
__global__ void csr_zero_kernel(int N) {
    for (int i = blockIdx.x * blockDim.x + threadIdx.x; i < N; i += gridDim.x * blockDim.x) {
        g_deg[i] = 0;
        g_cur[i] = 0;
    }
}
__global__ void csr_hist_kernel(const int* __restrict__ ei, int E) {
    for (int e = blockIdx.x * blockDim.x + threadIdx.x; e < E; e += gridDim.x * blockDim.x)
        atomicAdd(&g_deg[ei[e]], 1);
}
__global__ void csr_scan_local_kernel(int N) {
    __shared__ int sm[1024];
    int b = blockIdx.x, t = threadIdx.x;
    int i = b * 1024 + t;
    int v = (i < N) ? g_deg[i] : 0;
    sm[t] = v;
    __syncthreads();
#pragma unroll
    for (int off = 1; off < 1024; off <<= 1) {
        int x = sm[t];
        int y = (t >= off) ? sm[t - off] : 0;
        __syncthreads();
        sm[t] = x + y;
        __syncthreads();
    }
    if (i < N) g_off[i] = sm[t] - v;
    if (t == 1023) g_bsum[b] = sm[t];
}
__global__ void csr_scan_bsum_kernel(int nblk) {
    __shared__ int sm[256];
    int t = threadIdx.x;
    int v = (t < nblk) ? g_bsum[t] : 0;
    sm[t] = v;
    __syncthreads();
#pragma unroll
    for (int off = 1; off < 256; off <<= 1) {
        int x = sm[t];
        int y = (t >= off) ? sm[t - off] : 0;
        __syncthreads();
        sm[t] = x + y;
        __syncthreads();
    }
    g_bsum[t] = sm[t] - v;
}
__global__ void csr_scan_add_kernel(int N, int E) {
    int i = blockIdx.x * blockDim.x + threadIdx.x;
    if (i < N) g_off[i] += g_bsum[i >> 10];
    if (i == 0) g_off[N] = E;
}
__global__ void csr_fill_kernel(const int* __restrict__ ei, const float* __restrict__ wt, int E) {
    for (int e = blockIdx.x * blockDim.x + threadIdx.x; e < E; e += gridDim.x * blockDim.x) {
        int row = ei[e];
        int pos = g_off[row] + atomicAdd(&g_cur[row], 1);
        g_ccol[pos] = ei[E + e];
        g_cw[pos] = wt[e];
    }
}

// ---------------- gather: msg = A@ego (fp16 reads, 8-edge MLP), emit H fp16 ----------------
__global__ void gather_kernel(int sel, int N) {
    int g = blockIdx.x * blockDim.x + threadIdx.x;
    int n = g >> 5;
    if (n >= N) return;
    int lane = g & 31;
    int s = g_off[n], e = g_off[n + 1];
    const __half* __restrict__ ego = g_ego_h[sel];
    float4 acc = make_float4(0.f, 0.f, 0.f, 0.f);
    int i = s;
    for (; i + 8 <= e; i += 8) {
        int c[8];
        float w[8];
        uint2 r[8];
#pragma unroll
        for (int j = 0; j < 8; j++) c[j] = __ldg(g_ccol + i + j);
#pragma unroll
        for (int j = 0; j < 8; j++) w[j] = __ldg(g_cw + i + j);
#pragma unroll
        for (int j = 0; j < 8; j++)
            r[j] = __ldg((const uint2*)(ego + (size_t)c[j] * DIM) + lane);
#pragma unroll
        for (int j = 0; j < 8; j++) {
            float4 v = half4_to_f4(r[j]);
            acc.x += w[j] * v.x; acc.y += w[j] * v.y;
            acc.z += w[j] * v.z; acc.w += w[j] * v.w;
        }
    }
    if (i + 4 <= e) {
        int c0 = __ldg(g_ccol + i), c1 = __ldg(g_ccol + i + 1);
        int c2 = __ldg(g_ccol + i + 2), c3 = __ldg(g_ccol + i + 3);
        float w0 = __ldg(g_cw + i), w1 = __ldg(g_cw + i + 1);
        float w2 = __ldg(g_cw + i + 2), w3 = __ldg(g_cw + i + 3);
        uint2 r0 = __ldg((const uint2*)(ego + (size_t)c0 * DIM) + lane);
        uint2 r1 = __ldg((const uint2*)(ego + (size_t)c1 * DIM) + lane);
        uint2 r2 = __ldg((const uint2*)(ego + (size_t)c2 * DIM) + lane);
        uint2 r3 = __ldg((const uint2*)(ego + (size_t)c3 * DIM) + lane);
        float4 v0 = half4_to_f4(r0), v1 = half4_to_f4(r1);
        float4 v2 = half4_to_f4(r2), v3 = half4_to_f4(r3);
        acc.x += w0 * v0.x; acc.y += w0 * v0.y; acc.z += w0 * v0.z; acc.w += w0 * v0.w;
        acc.x += w1 * v1.x; acc.y += w1 * v1.y; acc.z += w1 * v1.z; acc.w += w1 * v1.w;
        acc.x += w2 * v2.x; acc.y += w2 * v2.y; acc.z += w2 * v2.z; acc.w += w2 * v2.w;
        acc.x += w3 * v3.x; acc.y += w3 * v3.y; acc.z += w3 * v3.z; acc.w += w3 * v3.w;
        i += 4;
    }
    for (; i < e; i++) {
        int c = __ldg(g_ccol + i);
        float w = __ldg(g_cw + i);
        float4 v = half4_to_f4(__ldg((const uint2*)(ego + (size_t)c * DIM) + lane));
        acc.x += w * v.x; acc.y += w * v.y; acc.z += w * v.z; acc.w += w * v.w;
    }
    float4 eg = half4_to_f4(__ldg((const uint2*)(ego + (size_t)n * DIM) + lane));
    float4 pr = make_float4(acc.x * eg.x, acc.y * eg.y, acc.z * eg.z, acc.w * eg.w);

    char* h_row = (char*)(g_h + (size_t)n * 256);
    *(uint2*)(h_row + lane * 8) = f4_to_half4(acc);
    *(uint2*)(h_row + 256 + lane * 8) = f4_to_half4(pr);
}

// ================= layer GEMM: pipelined cp.async + mma.sync fp16 (single pass) =================
// Block 128x128, K=256 in 4 stages of 64. 256 threads, 8 warps, warp tile 64x32. 2 CTAs/SM.
#define SMEM_B    0          // 65536 (4 kb tiles x 16KB, resident)
#define SMEM_A    65536      // 2 stages x 16KB
#define LK_SMEM   98304
#define EPI_ROWPART 69632    // float [128][4]
#define EPI_SCALE   71680    // float [128]

__device__ __forceinline__ void issue_a_stage(char* smem, int kb, int buf, int n0, int N, int tid) {
    uint32_t abase = smem_u32(smem + SMEM_A + buf * 16384);
    const char* hsrc = (const char*)g_h;
#pragma unroll
    for (int it = 0; it < 4; it++) {
        int idx = tid + 256 * it;           // 1024 chunks: [row 128][c 8]
        int row = idx >> 3, c = idx & 7;
        int n = n0 + row;
        uint32_t sz = (n < N) ? 16u : 0u;
        size_t so = (size_t)(n < N ? n : 0) * 512 + kb * 128 + c * 16;
        uint32_t ci = (uint32_t)(row * 8 + (c ^ (row & 7))) * 16;
        cp_async16(abase + ci, hsrc + so, sz);
    }
}

__global__ __launch_bounds__(256, 2) void layer_kernel(int outsel, int layer, int N, int write_ego) {
    extern __shared__ char smem[];
    const uint32_t sb = smem_u32(smem);
    const int tid = threadIdx.x;
    const int wid = tid >> 5;
    const int lid = tid & 31;
    const int n0 = blockIdx.x * 128;
    const int wm = wid >> 2;
    const int wn = wid & 3;

    // ---- resident B (full layer W fp16, 64KB) + A stages ----
    {
        const char* wsrc = (const char*)(g_wh) + (size_t)layer * 65536;
        uint32_t bb = sb + SMEM_B;
#pragma unroll
        for (int it = 0; it < 16; it++) {
            int idx = tid + 256 * it;       // 4096 chunks: [kb 4][row 128][c 8]
            int kb = idx >> 10;
            int r = (idx >> 3) & 127;
            int c = idx & 7;
            size_t so = (size_t)r * 512 + kb * 128 + c * 16;
            uint32_t ci = (uint32_t)(kb * 16384) + (uint32_t)(r * 8 + (c ^ (r & 7))) * 16;
            cp_async16(bb + ci, wsrc + so, 16);
        }
    }
    issue_a_stage(smem, 0, 0, n0, N, tid);
    CP_COMMIT();
    issue_a_stage(smem, 1, 1, n0, N, tid);
    CP_COMMIT();

    float acc[4][4][4];
#pragma unroll
    for (int mt = 0; mt < 4; mt++)
#pragma unroll
        for (int nt = 0; nt < 4; nt++)
#pragma unroll
            for (int c = 0; c < 4; c++) acc[mt][nt][c] = 0.f;

#pragma unroll
    for (int kb = 0; kb < 4; kb++) {
        if (kb < 3) CP_WAIT1(); else CP_WAIT0();
        __syncthreads();

        uint32_t abase = sb + SMEM_A + (kb & 1) * 16384;
        uint32_t bbase = sb + SMEM_B + kb * 16384;
#pragma unroll
        for (int ks = 0; ks < 4; ks++) {
            uint32_t a[4][4];
            int lr = lid & 15, lk = lid >> 4;
#pragma unroll
            for (int mt = 0; mt < 4; mt++) {
                int r = wm * 64 + mt * 16 + lr;
                int kc = ks * 2 + lk;
                uint32_t off = (uint32_t)(r * 8 + (kc ^ (r & 7))) * 16;
                LDSM_X4(a[mt], abase + off);
            }
            uint32_t b[2][4];
            int nr = (lid & 7) + ((lid >> 4) << 3);
            int nk = (lid >> 3) & 1;
#pragma unroll
            for (int np = 0; np < 2; np++) {
                int r = wn * 32 + np * 16 + nr;
                int kc = ks * 2 + nk;
                uint32_t off = (uint32_t)(r * 8 + (kc ^ (r & 7))) * 16;
                LDSM_X4(b[np], bbase + off);
            }
#pragma unroll
            for (int mt = 0; mt < 4; mt++)
#pragma unroll
                for (int nt = 0; nt < 4; nt++)
                    mma16816_f16(acc[mt][nt], a[mt], &b[nt >> 1][(nt & 1) * 2]);
        }
        __syncthreads();
        if (kb + 2 < 4) { issue_a_stage(smem, kb + 2, kb & 1, n0, N, tid); CP_COMMIT(); }
    }

    // ================= epilogue (reuses SMEM) =================
    float* stage = (float*)smem;                      // [128][136]
    float* rowpart = (float*)(smem + EPI_ROWPART);    // [128][4]
    const float* bias = g_bias + layer * 128;
    int qid = lid >> 2, qt = lid & 3;
#pragma unroll
    for (int mt = 0; mt < 4; mt++) {
        int rA = wm * 64 + mt * 16 + qid;
        int rB = rA + 8;
        float sqa = 0.f, sqb = 0.f;
#pragma unroll
        for (int nt = 0; nt < 4; nt++) {
            int col = wn * 32 + nt * 8 + 2 * qt;
            float b0 = __ldg(bias + col), b1 = __ldg(bias + col + 1);
            float* c = acc[mt][nt];
            float x0 = c[0] + b0, x1 = c[1] + b1;
            float y0 = c[2] + b0, y1 = c[3] + b1;
            x0 = x0 > 0.f ? x0 : 0.2f * x0;
            x1 = x1 > 0.f ? x1 : 0.2f * x1;
            y0 = y0 > 0.f ? y0 : 0.2f * y0;
            y1 = y1 > 0.f ? y1 : 0.2f * y1;
            stage[rA * 136 + col] = x0;
            stage[rA * 136 + col + 1] = x1;
            stage[rB * 136 + col] = y0;
            stage[rB * 136 + col + 1] = y1;
            sqa += x0 * x0 + x1 * x1;
            sqb += y0 * y0 + y1 * y1;
        }
        sqa += __shfl_xor_sync(0xffffffffu, sqa, 1);
        sqa += __shfl_xor_sync(0xffffffffu, sqa, 2);
        sqb += __shfl_xor_sync(0xffffffffu, sqb, 1);
        sqb += __shfl_xor_sync(0xffffffffu, sqb, 2);
        if (qt == 0) {
            rowpart[rA * 4 + wn] = sqa;
            rowpart[rB * 4 + wn] = sqb;
        }
    }
    __syncthreads();
    float* scl = (float*)(smem + EPI_SCALE);
    if (tid < 128) {
        float tot = rowpart[tid * 4] + rowpart[tid * 4 + 1] + rowpart[tid * 4 + 2] + rowpart[tid * 4 + 3];
        scl[tid] = 1.0f / fmaxf(sqrtf(tot), 1e-12f);
    }
    __syncthreads();
    __half* ego_out = g_ego_h[outsel];
#pragma unroll
    for (int it = 0; it < 16; it++) {
        int idx = tid + 256 * it;           // [128 rows][32 f4-chunks]
        int r = idx >> 5, j = idx & 31;
        int n = n0 + r;
        if (n < N) {
            float4 v = *(const float4*)(stage + r * 136 + j * 4);
            if (write_ego)
                ((uint2*)(ego_out + (size_t)n * DIM))[j] = f4_to_half4(v);
            float s = scl[r];
            float4 sv = make_float4(v.x * s, v.y * s, v.z * s, v.w * s);
            ((uint2*)(g_seg + (size_t)n * DIM))[j] = f4_to_half4(sv);
        }
    }
}

// ---------------- segment scoring: out[q] (+)= dot(row[s], row[d]) over 128 ----------------
// use_emb=1: fp32 emb input. else: fp16 g_seg (32 uint2 per row).
__global__ void score_seg_kernel(const int* __restrict__ eli, const float* __restrict__ emb,
                                 float* __restrict__ out, int Q, int use_emb, int add) {
    int g = blockIdx.x * blockDim.x + threadIdx.x;
    int q = g >> 3;
    if (q >= Q) return;
    int lane = g & 7;
    int s = __ldg(eli + q);
    int d = __ldg(eli + Q + q);
    float sum = 0.f;
    if (use_emb) {
        const float4* ps = (const float4*)(emb + (size_t)s * DIM);
        const float4* pd = (const float4*)(emb + (size_t)d * DIM);
#pragma unroll
        for (int t = 0; t < 4; t++) {
            float4 a = __ldg(ps + lane + 8 * t);
            float4 b = __ldg(pd + lane + 8 * t);
            sum += a.x * b.x + a.y * b.y + a.z * b.z + a.w * b.w;
        }
    } else {
        const uint2* ps = (const uint2*)(g_seg + (size_t)s * DIM);
        const uint2* pd = (const uint2*)(g_seg + (size_t)d * DIM);
#pragma unroll
        for (int t = 0; t < 4; t++) {          // FIXED: 4 x 8 lanes x 4 halves = 128
            float4 a = half4_to_f4(__ldg(ps + lane + 8 * t));
            float4 b = half4_to_f4(__ldg(pd + lane + 8 * t));
            sum += a.x * b.x + a.y * b.y + a.z * b.z + a.w * b.w;
        }
    }
    sum += __shfl_xor_sync(0xffffffffu, sum, 1);
    sum += __shfl_xor_sync(0xffffffffu, sum, 2);
    sum += __shfl_xor_sync(0xffffffffu, sum, 4);
    if (lane == 0) {
        if (add) out[q] += sum;
        else     out[q] = sum;
    }
}

// ---------------- launch ----------------
extern "C" void kernel_launch(void* const* d_in, const int* in_sizes, int n_in,
                              void* d_out, int out_size) {
    const int*   ei  = (const int*)d_in[0];
    const int*   eli = (const int*)d_in[1];
    const float* wt  = (const float*)d_in[2];
    const float* emb = (const float*)d_in[3];
    const float* gcw = (const float*)d_in[4];
    const float* gcb = (const float*)d_in[5];
    const float* biw = (const float*)d_in[6];
    const float* bib = (const float*)d_in[7];

    int E = in_sizes[2];
    int Q = in_sizes[1] / 2;
    int N = in_sizes[3] / DIM;

    static bool inited = false;
    static cudaStream_t s1;
    static cudaEvent_t evFork, evCsr, evScore[3], evJoin;
    if (!inited) {
        cudaFuncSetAttribute(layer_kernel, cudaFuncAttributeMaxDynamicSharedMemorySize, LK_SMEM);
        cudaStreamCreateWithFlags(&s1, cudaStreamNonBlocking);
        cudaEventCreateWithFlags(&evFork, cudaEventDisableTiming);
        cudaEventCreateWithFlags(&evCsr, cudaEventDisableTiming);
        for (int i = 0; i < 3; i++) cudaEventCreateWithFlags(&evScore[i], cudaEventDisableTiming);
        cudaEventCreateWithFlags(&evJoin, cudaEventDisableTiming);
        inited = true;
    }

    int nblk = (N + 1023) / 1024;
    int sblocks = (int)(((long long)Q * 8 + 255) / 256);

    // ---- fork: CSR build on s1, prep/init/score0 on s0 ----
    cudaEventRecord(evFork, 0);
    cudaStreamWaitEvent(s1, evFork, 0);

    csr_zero_kernel<<<256, 256, 0, s1>>>(N);
    csr_hist_kernel<<<1024, 256, 0, s1>>>(ei, E);
    csr_scan_local_kernel<<<nblk, 1024, 0, s1>>>(N);
    csr_scan_bsum_kernel<<<1, 256, 0, s1>>>(nblk);
    csr_scan_add_kernel<<<(N + 255) / 256, 256, 0, s1>>>(N, E);
    csr_fill_kernel<<<1024, 256, 0, s1>>>(ei, wt, E);
    cudaEventRecord(evCsr, s1);

    prep_kernel<<<(3 * 128 * 256 + 255) / 256, 256>>>(gcw, gcb, biw, bib);
    init_kernel<<<(N * 32 + 255) / 256, 256>>>(emb, N);
    score_seg_kernel<<<sblocks, 256>>>(eli, emb, (float*)d_out, Q, 1, 0);

    cudaStreamWaitEvent(0, evCsr, 0);

    for (int i = 0; i < 3; i++) {
        if (i >= 1) cudaStreamWaitEvent(0, evScore[i - 1], 0);
        long long gthreads = (long long)N * 32;
        int gblocks = (int)((gthreads + 255) / 256);
        gather_kernel<<<gblocks, 256>>>(i & 1 ? 1 : 0, N);
        layer_kernel<<<(N + 127) / 128, 256, LK_SMEM>>>((i + 1) & 1, i, N, i < 2 ? 1 : 0);
        cudaEventRecord(evScore[i], 0);   // marks layer i completion on s0
        cudaStreamWaitEvent(s1, evScore[i], 0);
        score_seg_kernel<<<sblocks, 256, 0, s1>>>(eli, emb, (float*)d_out, Q, 0, 1);
        cudaEventRecord(evScore[i], s1);  // re-record: now marks score i completion
    }
    cudaEventRecord(evJoin, s1);
    cudaStreamWaitEvent(0, evJoin, 0);
}